// round 11
// baseline (speedup 1.0000x reference)
#include <cuda_runtime.h>
#include <stdint.h>
#include <math.h>

// Problem constants
#define NB   2
#define TT   3000
#define CC   256
#define HH   256
#define FCH  8
#define DD   32
#define NF   (NB*FCH)          // 16 (n, head) pairs
#define MROW (NB*TT)           // 6000 combined GEMM rows
#define MW   96                // packed words per mask row (94 used)
#define QSCALE (0.17677669529663687f * 1.4426950408889634f)  // 1/sqrt(32)*log2(e)

// ---------------- scratch (static device globals: no allocations) ----------
__device__ float    g_q0[NF*TT*DD];
__device__ float    g_v0[NF*TT*DD];
__device__ float    g_q1[NF*TT*DD];
__device__ float    g_v1[NF*TT*DD];
__device__ float    g_m0[NF*TT*DD];
__device__ float    g_m1[NF*TT*DD];
// precomputed tf32 splits (bit patterns stored as float)
__device__ float    g_kh0[NF*TT*DD], g_kl0[NF*TT*DD];   // q0 as K operand
__device__ float    g_kh1[NF*TT*DD], g_kl1[NF*TT*DD];   // q1 as K operand
__device__ float    g_vh0[NF*TT*DD], g_vh1[NF*TT*DD];   // v hi only
// word-major packed masks: [n][word][row]
__device__ unsigned g_mb0[(size_t)NB*MW*TT];
__device__ unsigned g_mb1[(size_t)NB*MW*TT];
__device__ int      g_mask_kind;               // 0=u8, 1=i32, 2=f32, 3=bf16

// ---------------- helpers --------------------------------------------------
__device__ __forceinline__ float asf(uint32_t u) { return __uint_as_float(u); }
__device__ __forceinline__ uint32_t fui(float f) { return __float_as_uint(f); }

__device__ __forceinline__ uint32_t tf32r(float x) {
    uint32_t u;
    asm("cvt.rna.tf32.f32 %0, %1;" : "=r"(u) : "f"(x));
    return u;
}

__device__ __forceinline__ float ex2f(float x) {
    float y;
    asm("ex2.approx.ftz.f32 %0, %1;" : "=f"(y) : "f"(x));
    return y;
}

__device__ __forceinline__ void cp16(void* sdst, const void* gsrc) {
    unsigned d = (unsigned)__cvta_generic_to_shared(sdst);
    asm volatile("cp.async.cg.shared.global [%0], [%1], 16;" :: "r"(d), "l"(gsrc));
}

__device__ __forceinline__ float2 ffma2(float2 a, float2 b, float2 c) {
    unsigned long long ua = *reinterpret_cast<unsigned long long*>(&a);
    unsigned long long ub = *reinterpret_cast<unsigned long long*>(&b);
    unsigned long long uc = *reinterpret_cast<unsigned long long*>(&c);
    unsigned long long ud;
    asm("fma.rn.f32x2 %0, %1, %2, %3;" : "=l"(ud) : "l"(ua), "l"(ub), "l"(uc));
    return *reinterpret_cast<float2*>(&ud);
}

// m16n8k8 tf32 mma: D += A*B  (fp32 accum)
__device__ __forceinline__ void mma_tf32(float& d0, float& d1, float& d2, float& d3,
                                         uint32_t a0, uint32_t a1, uint32_t a2, uint32_t a3,
                                         uint32_t b0, uint32_t b1) {
    asm("mma.sync.aligned.m16n8k8.row.col.f32.tf32.tf32.f32 "
        "{%0,%1,%2,%3},{%4,%5,%6,%7},{%8,%9},{%0,%1,%2,%3};"
        : "+f"(d0), "+f"(d1), "+f"(d2), "+f"(d3)
        : "r"(a0), "r"(a1), "r"(a2), "r"(a3), "r"(b0), "r"(b1));
}

// ============================================================================
// 0) Mask dtype detection (fingerprint raw words; scan 1MB)
// ============================================================================
__global__ void detect_kernel(const unsigned* __restrict__ m)
{
    __shared__ int sF, sB, sH;
    if (threadIdx.x == 0) { sF = 0; sB = 0; sH = 0; }
    __syncthreads();
    int f = 0, b = 0, h = 0;
    for (int i = threadIdx.x; i < 262144; i += blockDim.x) {
        unsigned w = m[i];
        if (w == 0x3F803F80u || w == 0x00003F80u) h = 1;
        else if (w == 0x3F800000u) f = 1;
        else if (w > 1u) b = 1;
    }
    if (f) sF = 1;
    if (b) sB = 1;
    if (h) sH = 1;
    __syncthreads();
    if (threadIdx.x == 0)
        g_mask_kind = sH ? 3 : (sF ? 2 : (sB ? 0 : 1));
}

// ============================================================================
// 0b) Pack mask into word-major bit arrays for both orientations.
//     grid (94, 94, 2), block (32, 32).
// ============================================================================
__global__ void pack_kernel(const void* __restrict__ m)
{
    __shared__ uint8_t tile[32][33];
    const int kind = g_mask_kind;
    const int n  = blockIdx.z;
    const int l0 = blockIdx.y * 32, s0 = blockIdx.x * 32;
    const int tx = threadIdx.x, ty = threadIdx.y;
    const int l = l0 + ty, s = s0 + tx;

    bool val = false;
    if (l < TT && s < TT) {
        size_t idx = ((size_t)n * TT + l) * TT + s;
        if      (kind == 0) val = ((const uint8_t*)m)[idx] != 0;
        else if (kind == 1) val = ((const int*)m)[idx] != 0;
        else if (kind == 2) val = ((const float*)m)[idx] != 0.0f;
        else                val = ((const unsigned short*)m)[idx] != 0;
    }

    unsigned w0 = __ballot_sync(0xFFFFFFFFu, val);
    if (tx == 0 && l < TT)
        g_mb0[((size_t)n * MW + blockIdx.x) * TT + l] = w0;

    tile[ty][tx] = val ? 1 : 0;
    __syncthreads();

    bool valT = tile[tx][ty] != 0;
    unsigned w1 = __ballot_sync(0xFFFFFFFFu, valT);
    if (tx == 0 && (s0 + ty) < TT)
        g_mb1[((size_t)n * MW + blockIdx.y) * TT + s0 + ty] = w1;
}

// ============================================================================
// 1) Projection: p = x @ W_proj + b_proj -> per-head q/v layout
//    grid (8, 94, 2) block 256.  f32x2 inner product.
// ============================================================================
__global__ void proj_kernel(const float* __restrict__ x0,
                            const float* __restrict__ x1,
                            const float* __restrict__ W,
                            const float* __restrict__ bias)
{
    const float* x  = blockIdx.z ? x1 : x0;
    float*       qh = blockIdx.z ? g_q1 : g_q0;
    float*       vh = blockIdx.z ? g_v1 : g_v0;

    __shared__ float As[16][68];
    __shared__ float Bs[16][64];

    const int tid = threadIdx.x;
    const int tx = tid & 15, ty = tid >> 4;
    const int bm = blockIdx.y * 64, bn = blockIdx.x * 64;

    const int arow = tid >> 2, akc = (tid & 3) * 4;
    const int brow = tid >> 4, bnc = (tid & 15) * 4;

    float2 c2[4][2];
    #pragma unroll
    for (int i = 0; i < 4; ++i) { c2[i][0] = make_float2(0.f,0.f); c2[i][1] = make_float2(0.f,0.f); }

    for (int kt = 0; kt < CC; kt += 16) {
        int gr = bm + arow;
        float4 av = make_float4(0.f, 0.f, 0.f, 0.f);
        if (gr < MROW) av = *(const float4*)(x + (size_t)gr * CC + kt + akc);
        As[akc + 0][arow] = av.x;
        As[akc + 1][arow] = av.y;
        As[akc + 2][arow] = av.z;
        As[akc + 3][arow] = av.w;
        *(float4*)&Bs[brow][bnc] =
            *(const float4*)(W + (size_t)(kt + brow) * (2 * HH) + bn + bnc);
        __syncthreads();
        #pragma unroll
        for (int k = 0; k < 16; ++k) {
            float4 a  = *(float4*)&As[k][ty * 4];
            float4 bv = *(float4*)&Bs[k][tx * 4];
            float2 b01 = make_float2(bv.x, bv.y), b23 = make_float2(bv.z, bv.w);
            c2[0][0] = ffma2(make_float2(a.x,a.x), b01, c2[0][0]);
            c2[0][1] = ffma2(make_float2(a.x,a.x), b23, c2[0][1]);
            c2[1][0] = ffma2(make_float2(a.y,a.y), b01, c2[1][0]);
            c2[1][1] = ffma2(make_float2(a.y,a.y), b23, c2[1][1]);
            c2[2][0] = ffma2(make_float2(a.z,a.z), b01, c2[2][0]);
            c2[2][1] = ffma2(make_float2(a.z,a.z), b23, c2[2][1]);
            c2[3][0] = ffma2(make_float2(a.w,a.w), b01, c2[3][0]);
            c2[3][1] = ffma2(make_float2(a.w,a.w), b23, c2[3][1]);
        }
        __syncthreads();
    }

    #pragma unroll
    for (int i = 0; i < 4; ++i) {
        int gr = bm + ty * 4 + i;
        if (gr >= MROW) continue;
        int n = gr / TT, t = gr % TT;
        float cv[4] = { c2[i][0].x, c2[i][0].y, c2[i][1].x, c2[i][1].y };
        #pragma unroll
        for (int j = 0; j < 4; ++j) {
            int gc = bn + tx * 4 + j;
            float v = cv[j] + bias[gc];
            int cc = gc & 255;
            int f = cc >> 5, d = cc & 31;
            float* dst = (gc < HH) ? qh : vh;
            dst[((size_t)(n * FCH + f) * TT + t) * DD + d] = v;
        }
    }
}

// ============================================================================
// 1b) Precompute tf32 hi/lo splits of K operands (q arrays, raw) and hi of V.
//     grid 6000 block 256.
// ============================================================================
__global__ void split_kernel()
{
    int i = blockIdx.x * 256 + threadIdx.x;
    if (i >= NF * TT * DD) return;
    float a; uint32_t h;
    a = g_q0[i]; h = tf32r(a);
    g_kh0[i] = asf(h); g_kl0[i] = asf(tf32r(a - asf(h)));
    a = g_q1[i]; h = tf32r(a);
    g_kh1[i] = asf(h); g_kl1[i] = asf(tf32r(a - asf(h)));
    g_vh0[i] = asf(tf32r(g_v0[i]));
    g_vh1[i] = asf(tf32r(g_v1[i]));
}

// ============================================================================
// 2) Flash attention on tensor cores. Pre-split tf32 K/V operands from gmem.
//    QK: 3xTF32.  PV: 2-term (Ph*Vh + Pl*Vh).  No-max softmax.
//    Block = 4 warps, BR=64 (16 rows/warp), BC=48 (63 tiles).
//    grid (47, 16, 2) block 128.  smem 45KB -> 5 blocks/SM.
// ============================================================================
__global__ void __launch_bounds__(128)
flashmma_kernel()
{
    const int dir  = blockIdx.z;
    const float*    Q  = dir ? g_q1  : g_q0;
    const float*    KH = dir ? g_kh0 : g_kh1;
    const float*    KL = dir ? g_kl0 : g_kl1;
    const float*    VH = dir ? g_vh0 : g_vh1;
    const unsigned* Mb = dir ? g_mb1 : g_mb0;
    float*          O  = dir ? g_m1  : g_m0;

    const int head = blockIdx.y;          // 0..15
    const int n    = head >> 3;
    const int tid  = threadIdx.x;
    const int wid  = tid >> 5;
    const int lane = tid & 31;
    const int g    = lane >> 2;           // groupID
    const int tg   = lane & 3;            // thread-in-group

    const int r0 = blockIdx.x * 64 + wid * 16 + g;   // < 3000 always
    const int r1 = r0 + 8;
    const int rB = (r1 < TT) ? r1 : (TT - 1);

    // strides: K 36 (4r+c mod32 distinct), V 40 (8r+c mod32 distinct): bank-clean
    __shared__ __align__(16) float Khs[2][48 * 36];
    __shared__ __align__(16) float Kls[2][48 * 36];
    __shared__ __align__(16) float Vhs[2][48 * 40];
    __shared__ __align__(16) float Ps[4][16 * 12];

    const float* Qh  = Q  + (size_t)head * TT * DD;
    const float* KHh = KH + (size_t)head * TT * DD;
    const float* KLh = KL + (size_t)head * TT * DD;
    const float* VHh = VH + (size_t)head * TT * DD;

    // ---- Q fragments: scale by 1/sqrt(d)*log2e, hi/lo tf32 split (once) ----
    uint32_t qhf[4][4], qlf[4][4];
    #pragma unroll
    for (int c = 0; c < 4; ++c) {
        int col = c * 8 + tg;
        float v[4];
        v[0] = Qh[(size_t)r0 * DD + col]     * QSCALE;
        v[1] = Qh[(size_t)rB * DD + col]     * QSCALE;
        v[2] = Qh[(size_t)r0 * DD + col + 4] * QSCALE;
        v[3] = Qh[(size_t)rB * DD + col + 4] * QSCALE;
        #pragma unroll
        for (int i = 0; i < 4; ++i) {
            qhf[c][i] = tf32r(v[i]);
            qlf[c][i] = tf32r(v[i] - asf(qhf[c][i]));
        }
    }

    auto load_tile = [&](int tile, int buf) {
        int s0 = tile * 48;
        #pragma unroll
        for (int k = 0; k < 3; ++k) {
            int idx = tid + k * 128;             // 384 chunks: 48 rows x 8
            int s = idx >> 3, dc = (idx & 7) * 4;
            int sg = s0 + s;
            if (sg < TT) {
                size_t off = (size_t)sg * DD + dc;
                cp16(&Khs[buf][s * 36 + dc], KHh + off);
                cp16(&Kls[buf][s * 36 + dc], KLh + off);
                cp16(&Vhs[buf][s * 40 + dc], VHh + off);
            } else {
                float4 z = make_float4(0.f, 0.f, 0.f, 0.f);
                *(float4*)&Khs[buf][s * 36 + dc] = z;
                *(float4*)&Kls[buf][s * 36 + dc] = z;
                *(float4*)&Vhs[buf][s * 40 + dc] = z;
            }
        }
        asm volatile("cp.async.commit_group;" ::: "memory");
    };

    load_tile(0, 0);

    float o[4][4];
    #pragma unroll
    for (int i = 0; i < 4; ++i)
        #pragma unroll
        for (int j = 0; j < 4; ++j) o[i][j] = 0.f;
    float lr0 = 0.f, lr1 = 0.f;

    const unsigned* mbase = Mb + (size_t)n * MW * TT;
    float* Pw = &Ps[wid][0];

    for (int tile = 0; tile < 63; ++tile) {
        const int buf = tile & 1;
        if (tile + 1 < 63) {
            load_tile(tile + 1, buf ^ 1);
            asm volatile("cp.async.wait_group 1;" ::: "memory");
        } else {
            asm volatile("cp.async.wait_group 0;" ::: "memory");
        }
        __syncthreads();

        // mask bits: s0=48*tile, sh in {0,16}, window fits 2 words
        const int s0 = tile * 48;
        const int w0 = s0 >> 5, sh = s0 & 31;
        unsigned long long mv0 =
            ((unsigned long long)mbase[(size_t)(w0 + 1) * TT + r0] << 32) |
             (unsigned long long)mbase[(size_t)w0 * TT + r0];
        unsigned long long mv1 =
            ((unsigned long long)mbase[(size_t)(w0 + 1) * TT + rB] << 32) |
             (unsigned long long)mbase[(size_t)w0 * TT + rB];
        mv0 >>= sh; mv1 >>= sh;

        const float* Khb = &Khs[buf][0];
        const float* Klb = &Kls[buf][0];
        const float* Vhb = &Vhs[buf][0];

        #pragma unroll 2
        for (int j = 0; j < 6; ++j) {
            // ---- QK^T for s-cols [j*8, j*8+8): 3xTF32, K pre-split ----
            float c0 = 0.f, c1 = 0.f, c2 = 0.f, c3 = 0.f;
            #pragma unroll
            for (int cc = 0; cc < 4; ++cc) {
                int ki = (j * 8 + g) * 36 + cc * 8 + tg;
                uint32_t bh0 = fui(Khb[ki]), bh1 = fui(Khb[ki + 4]);
                uint32_t bl0 = fui(Klb[ki]), bl1 = fui(Klb[ki + 4]);
                mma_tf32(c0, c1, c2, c3, qhf[cc][0], qhf[cc][1], qhf[cc][2], qhf[cc][3], bh0, bh1);
                mma_tf32(c0, c1, c2, c3, qlf[cc][0], qlf[cc][1], qlf[cc][2], qlf[cc][3], bh0, bh1);
                mma_tf32(c0, c1, c2, c3, qhf[cc][0], qhf[cc][1], qhf[cc][2], qhf[cc][3], bl0, bl1);
            }

            // ---- masked exp (no-max: scores bounded) ----
            int base = j * 8 + 2 * tg;
            float p0 = ((mv0 >> base)       & 1ULL) ? ex2f(c0) : 0.f;
            float p1 = ((mv0 >> (base + 1)) & 1ULL) ? ex2f(c1) : 0.f;
            float p2 = ((mv1 >> base)       & 1ULL) ? ex2f(c2) : 0.f;
            float p3 = ((mv1 >> (base + 1)) & 1ULL) ? ex2f(c3) : 0.f;
            lr0 += p0 + p1;
            lr1 += p2 + p3;

            // ---- redistribute P (C-layout -> A-layout) via mini-P smem ----
            *(float2*)&Pw[g * 12 + 2 * tg]       = make_float2(p0, p1);
            *(float2*)&Pw[(g + 8) * 12 + 2 * tg] = make_float2(p2, p3);
            __syncwarp();
            float a0r = Pw[g * 12 + tg];
            float a1r = Pw[(g + 8) * 12 + tg];
            float a2r = Pw[g * 12 + tg + 4];
            float a3r = Pw[(g + 8) * 12 + tg + 4];
            uint32_t ah0 = tf32r(a0r), ah1 = tf32r(a1r), ah2 = tf32r(a2r), ah3 = tf32r(a3r);
            uint32_t al0 = tf32r(a0r - asf(ah0)), al1 = tf32r(a1r - asf(ah1)),
                     al2 = tf32r(a2r - asf(ah2)), al3 = tf32r(a3r - asf(ah3));

            // ---- PV: O[16x32] += P[16x8] * V[8x32], 2-term (V pre-tf32) ----
            #pragma unroll
            for (int nt = 0; nt < 4; ++nt) {
                uint32_t vh0 = fui(Vhb[(j * 8 + tg) * 40 + nt * 8 + g]);
                uint32_t vh1 = fui(Vhb[(j * 8 + tg + 4) * 40 + nt * 8 + g]);
                mma_tf32(o[nt][0], o[nt][1], o[nt][2], o[nt][3], ah0, ah1, ah2, ah3, vh0, vh1);
                mma_tf32(o[nt][0], o[nt][1], o[nt][2], o[nt][3], al0, al1, al2, al3, vh0, vh1);
            }
            __syncwarp();
        }
        __syncthreads();   // protect buffers before next prefetch overwrites
    }

    // ---- row sums over the 4 threads sharing each row ----
    lr0 += __shfl_xor_sync(0xFFFFFFFFu, lr0, 1);
    lr0 += __shfl_xor_sync(0xFFFFFFFFu, lr0, 2);
    lr1 += __shfl_xor_sync(0xFFFFFFFFu, lr1, 1);
    lr1 += __shfl_xor_sync(0xFFFFFFFFu, lr1, 2);
    float inv0 = (lr0 > 0.f) ? 1.f / lr0 : 0.f;   // all-masked row -> 0
    float inv1 = (lr1 > 0.f) ? 1.f / lr1 : 0.f;

    float* Oh = O + (size_t)head * TT * DD;
    #pragma unroll
    for (int nt = 0; nt < 4; ++nt) {
        int d0 = nt * 8 + 2 * tg;
        *(float2*)&Oh[(size_t)r0 * DD + d0] =
            make_float2(o[nt][0] * inv0, o[nt][1] * inv0);
        if (r1 < TT)
            *(float2*)&Oh[(size_t)r1 * DD + d0] =
                make_float2(o[nt][2] * inv1, o[nt][3] * inv1);
    }
}

// ============================================================================
// 3) Merge: out = concat_heads(m) @ W_merge + b_merge
//    grid (4, 94, 2) block 256.  f32x2 inner product.
// ============================================================================
__global__ void merge_kernel(const float* __restrict__ W,
                             const float* __restrict__ bias,
                             float* __restrict__ out)
{
    const float* A = blockIdx.z ? g_m1 : g_m0;
    float* o = out + (size_t)blockIdx.z * MROW * CC;

    __shared__ float As[16][68];
    __shared__ float Bs[16][64];

    const int tid = threadIdx.x;
    const int tx = tid & 15, ty = tid >> 4;
    const int bm = blockIdx.y * 64, bn = blockIdx.x * 64;

    const int arow = tid >> 2, akc = (tid & 3) * 4;
    const int brow = tid >> 4, bnc = (tid & 15) * 4;

    float2 c2[4][2];
    #pragma unroll
    for (int i = 0; i < 4; ++i) { c2[i][0] = make_float2(0.f,0.f); c2[i][1] = make_float2(0.f,0.f); }

    for (int kt = 0; kt < HH; kt += 16) {
        int gr = bm + arow;
        int gk = kt + akc;                    // hidden index = f*32 + d
        float4 av = make_float4(0.f, 0.f, 0.f, 0.f);
        if (gr < MROW) {
            int n = gr / TT, t = gr % TT;
            int f = gk >> 5, d = gk & 31;
            av = *(const float4*)(A + ((size_t)(n * FCH + f) * TT + t) * DD + d);
        }
        As[akc + 0][arow] = av.x;
        As[akc + 1][arow] = av.y;
        As[akc + 2][arow] = av.z;
        As[akc + 3][arow] = av.w;
        *(float4*)&Bs[brow][bnc] =
            *(const float4*)(W + (size_t)(kt + brow) * CC + bn + bnc);
        __syncthreads();
        #pragma unroll
        for (int k = 0; k < 16; ++k) {
            float4 a  = *(float4*)&As[k][ty * 4];
            float4 bv = *(float4*)&Bs[k][tx * 4];
            float2 b01 = make_float2(bv.x, bv.y), b23 = make_float2(bv.z, bv.w);
            c2[0][0] = ffma2(make_float2(a.x,a.x), b01, c2[0][0]);
            c2[0][1] = ffma2(make_float2(a.x,a.x), b23, c2[0][1]);
            c2[1][0] = ffma2(make_float2(a.y,a.y), b01, c2[1][0]);
            c2[1][1] = ffma2(make_float2(a.y,a.y), b23, c2[1][1]);
            c2[2][0] = ffma2(make_float2(a.z,a.z), b01, c2[2][0]);
            c2[2][1] = ffma2(make_float2(a.z,a.z), b23, c2[2][1]);
            c2[3][0] = ffma2(make_float2(a.w,a.w), b01, c2[3][0]);
            c2[3][1] = ffma2(make_float2(a.w,a.w), b23, c2[3][1]);
        }
        __syncthreads();
    }

    #pragma unroll
    for (int i = 0; i < 4; ++i) {
        int gr = bm + ty * 4 + i;
        if (gr >= MROW) continue;
        float cv[4] = { c2[i][0].x, c2[i][0].y, c2[i][1].x, c2[i][1].y };
        #pragma unroll
        for (int j = 0; j < 4; ++j) {
            int gc = bn + tx * 4 + j;
            o[(size_t)gr * CC + gc] = cv[j] + bias[gc];
        }
    }
}

// ============================================================================
// launch
// ============================================================================
extern "C" void kernel_launch(void* const* d_in, const int* in_sizes, int n_in,
                              void* d_out, int out_size)
{
    const float* x0   = (const float*)d_in[0];
    const float* x1   = (const float*)d_in[1];
    const void*  mask = (const void*)d_in[2];
    const float* Wp   = (const float*)d_in[3];
    const float* bp   = (const float*)d_in[4];
    const float* Wm   = (const float*)d_in[5];
    const float* bmg  = (const float*)d_in[6];
    float* out = (float*)d_out;

    // 0) mask dtype detect + bit-pack both orientations (word-major)
    detect_kernel<<<1, 256>>>((const unsigned*)mask);
    pack_kernel<<<dim3(94, 94, 2), dim3(32, 32)>>>(mask);

    // 1) projection + head split, then precompute tf32 operand splits
    proj_kernel<<<dim3(8, 94, 2), 256>>>(x0, x1, Wp, bp);
    split_kernel<<<6000, 256>>>();

    // 2) bidirectional flash attention on tensor cores
    flashmma_kernel<<<dim3(47, NF, 2), 128>>>();

    // 3) merge heads + output projection (m0 -> first half, m1 -> second)
    merge_kernel<<<dim3(4, 94, 2), 256>>>(Wm, bmg, out);
}

// round 12
// speedup vs baseline: 1.5270x; 1.5270x over previous
#include <cuda_runtime.h>
#include <stdint.h>
#include <math.h>

// Problem constants
#define NB   2
#define TT   3000
#define CC   256
#define HH   256
#define FCH  8
#define DD   32
#define NF   (NB*FCH)          // 16 (n, head) pairs
#define MROW (NB*TT)           // 6000 combined GEMM rows
#define MW   96                // packed words per mask row (94 used)
#define QSCALE (0.17677669529663687f * 1.4426950408889634f)  // 1/sqrt(32)*log2(e)

// ---------------- scratch (static device globals: no allocations) ----------
__device__ float    g_q0[NF*TT*DD];
__device__ float    g_v0[NF*TT*DD];
__device__ float    g_q1[NF*TT*DD];
__device__ float    g_v1[NF*TT*DD];
__device__ float    g_m0[NF*TT*DD];
__device__ float    g_m1[NF*TT*DD];
// word-major packed masks: [n][word][row]
__device__ unsigned g_mb0[(size_t)NB*MW*TT];
__device__ unsigned g_mb1[(size_t)NB*MW*TT];
__device__ int      g_mask_kind;               // 0=u8, 1=i32, 2=f32, 3=bf16

// ---------------- helpers --------------------------------------------------
__device__ __forceinline__ float asf(uint32_t u) { return __uint_as_float(u); }

__device__ __forceinline__ uint32_t tf32r(float x) {
    uint32_t u;
    asm("cvt.rna.tf32.f32 %0, %1;" : "=r"(u) : "f"(x));
    return u;
}

__device__ __forceinline__ float ex2f(float x) {
    float y;
    asm("ex2.approx.ftz.f32 %0, %1;" : "=f"(y) : "f"(x));
    return y;
}

__device__ __forceinline__ void cp16(void* sdst, const void* gsrc) {
    unsigned d = (unsigned)__cvta_generic_to_shared(sdst);
    asm volatile("cp.async.cg.shared.global [%0], [%1], 16;" :: "r"(d), "l"(gsrc));
}

__device__ __forceinline__ float2 ffma2(float2 a, float2 b, float2 c) {
    unsigned long long ua = *reinterpret_cast<unsigned long long*>(&a);
    unsigned long long ub = *reinterpret_cast<unsigned long long*>(&b);
    unsigned long long uc = *reinterpret_cast<unsigned long long*>(&c);
    unsigned long long ud;
    asm("fma.rn.f32x2 %0, %1, %2, %3;" : "=l"(ud) : "l"(ua), "l"(ub), "l"(uc));
    return *reinterpret_cast<float2*>(&ud);
}

// m16n8k8 tf32 mma: D += A*B  (fp32 accum)
__device__ __forceinline__ void mma_tf32(float& d0, float& d1, float& d2, float& d3,
                                         uint32_t a0, uint32_t a1, uint32_t a2, uint32_t a3,
                                         uint32_t b0, uint32_t b1) {
    asm("mma.sync.aligned.m16n8k8.row.col.f32.tf32.tf32.f32 "
        "{%0,%1,%2,%3},{%4,%5,%6,%7},{%8,%9},{%0,%1,%2,%3};"
        : "+f"(d0), "+f"(d1), "+f"(d2), "+f"(d3)
        : "r"(a0), "r"(a1), "r"(a2), "r"(a3), "r"(b0), "r"(b1));
}

// ============================================================================
// 0) Mask dtype detection (fingerprint raw words; scan 1MB)
// ============================================================================
__global__ void detect_kernel(const unsigned* __restrict__ m)
{
    __shared__ int sF, sB, sH;
    if (threadIdx.x == 0) { sF = 0; sB = 0; sH = 0; }
    __syncthreads();
    int f = 0, b = 0, h = 0;
    for (int i = threadIdx.x; i < 262144; i += blockDim.x) {
        unsigned w = m[i];
        if (w == 0x3F803F80u || w == 0x00003F80u) h = 1;
        else if (w == 0x3F800000u) f = 1;
        else if (w > 1u) b = 1;
    }
    if (f) sF = 1;
    if (b) sB = 1;
    if (h) sH = 1;
    __syncthreads();
    if (threadIdx.x == 0)
        g_mask_kind = sH ? 3 : (sF ? 2 : (sB ? 0 : 1));
}

// ============================================================================
// 0b) Pack mask into word-major bit arrays for both orientations.
//     grid (94, 94, 2), block (32, 32).
// ============================================================================
__global__ void pack_kernel(const void* __restrict__ m)
{
    __shared__ uint8_t tile[32][33];
    const int kind = g_mask_kind;
    const int n  = blockIdx.z;
    const int l0 = blockIdx.y * 32, s0 = blockIdx.x * 32;
    const int tx = threadIdx.x, ty = threadIdx.y;
    const int l = l0 + ty, s = s0 + tx;

    bool val = false;
    if (l < TT && s < TT) {
        size_t idx = ((size_t)n * TT + l) * TT + s;
        if      (kind == 0) val = ((const uint8_t*)m)[idx] != 0;
        else if (kind == 1) val = ((const int*)m)[idx] != 0;
        else if (kind == 2) val = ((const float*)m)[idx] != 0.0f;
        else                val = ((const unsigned short*)m)[idx] != 0;
    }

    unsigned w0 = __ballot_sync(0xFFFFFFFFu, val);
    if (tx == 0 && l < TT)
        g_mb0[((size_t)n * MW + blockIdx.x) * TT + l] = w0;

    tile[ty][tx] = val ? 1 : 0;
    __syncthreads();

    bool valT = tile[tx][ty] != 0;
    unsigned w1 = __ballot_sync(0xFFFFFFFFu, valT);
    if (tx == 0 && (s0 + ty) < TT)
        g_mb1[((size_t)n * MW + blockIdx.y) * TT + s0 + ty] = w1;
}

// ============================================================================
// 1) Projection: p = x @ W_proj + b_proj -> per-head q/v layout
//    grid (8, 94, 2) block 256.  f32x2 inner product.
// ============================================================================
__global__ void proj_kernel(const float* __restrict__ x0,
                            const float* __restrict__ x1,
                            const float* __restrict__ W,
                            const float* __restrict__ bias)
{
    const float* x  = blockIdx.z ? x1 : x0;
    float*       qh = blockIdx.z ? g_q1 : g_q0;
    float*       vh = blockIdx.z ? g_v1 : g_v0;

    __shared__ float As[16][68];
    __shared__ float Bs[16][64];

    const int tid = threadIdx.x;
    const int tx = tid & 15, ty = tid >> 4;
    const int bm = blockIdx.y * 64, bn = blockIdx.x * 64;

    const int arow = tid >> 2, akc = (tid & 3) * 4;
    const int brow = tid >> 4, bnc = (tid & 15) * 4;

    float2 c2[4][2];
    #pragma unroll
    for (int i = 0; i < 4; ++i) { c2[i][0] = make_float2(0.f,0.f); c2[i][1] = make_float2(0.f,0.f); }

    for (int kt = 0; kt < CC; kt += 16) {
        int gr = bm + arow;
        float4 av = make_float4(0.f, 0.f, 0.f, 0.f);
        if (gr < MROW) av = *(const float4*)(x + (size_t)gr * CC + kt + akc);
        As[akc + 0][arow] = av.x;
        As[akc + 1][arow] = av.y;
        As[akc + 2][arow] = av.z;
        As[akc + 3][arow] = av.w;
        *(float4*)&Bs[brow][bnc] =
            *(const float4*)(W + (size_t)(kt + brow) * (2 * HH) + bn + bnc);
        __syncthreads();
        #pragma unroll
        for (int k = 0; k < 16; ++k) {
            float4 a  = *(float4*)&As[k][ty * 4];
            float4 bv = *(float4*)&Bs[k][tx * 4];
            float2 b01 = make_float2(bv.x, bv.y), b23 = make_float2(bv.z, bv.w);
            c2[0][0] = ffma2(make_float2(a.x,a.x), b01, c2[0][0]);
            c2[0][1] = ffma2(make_float2(a.x,a.x), b23, c2[0][1]);
            c2[1][0] = ffma2(make_float2(a.y,a.y), b01, c2[1][0]);
            c2[1][1] = ffma2(make_float2(a.y,a.y), b23, c2[1][1]);
            c2[2][0] = ffma2(make_float2(a.z,a.z), b01, c2[2][0]);
            c2[2][1] = ffma2(make_float2(a.z,a.z), b23, c2[2][1]);
            c2[3][0] = ffma2(make_float2(a.w,a.w), b01, c2[3][0]);
            c2[3][1] = ffma2(make_float2(a.w,a.w), b23, c2[3][1]);
        }
        __syncthreads();
    }

    #pragma unroll
    for (int i = 0; i < 4; ++i) {
        int gr = bm + ty * 4 + i;
        if (gr >= MROW) continue;
        int n = gr / TT, t = gr % TT;
        float cv[4] = { c2[i][0].x, c2[i][0].y, c2[i][1].x, c2[i][1].y };
        #pragma unroll
        for (int j = 0; j < 4; ++j) {
            int gc = bn + tx * 4 + j;
            float v = cv[j] + bias[gc];
            int cc = gc & 255;
            int f = cc >> 5, d = cc & 31;
            float* dst = (gc < HH) ? qh : vh;
            dst[((size_t)(n * FCH + f) * TT + t) * DD + d] = v;
        }
    }
}

// ============================================================================
// 2) Flash attention on tensor cores (round-10 skeleton: BC=64, raw K/V).
//    QK: 3xTF32 (on-the-fly K split).  PV: 1-term tf32(P)*tf32(V).
//    Block = 4 warps; 16 q-rows/warp (BR=64), BC=64 per tile, 47 tiles.
//    grid (47, 16, 2) block 128.
// ============================================================================
__global__ void __launch_bounds__(128)
flashmma_kernel()
{
    const int dir  = blockIdx.z;
    const float*    Q  = dir ? g_q1 : g_q0;
    const float*    Kg = dir ? g_q0 : g_q1;
    const float*    Vg = dir ? g_v0 : g_v1;
    const unsigned* Mb = dir ? g_mb1 : g_mb0;
    float*          O  = dir ? g_m1 : g_m0;

    const int head = blockIdx.y;          // 0..15
    const int n    = head >> 3;
    const int tid  = threadIdx.x;
    const int wid  = tid >> 5;
    const int lane = tid & 31;
    const int g    = lane >> 2;           // groupID (row within 8)
    const int tg   = lane & 3;            // thread-in-group

    const int r0 = blockIdx.x * 64 + wid * 16 + g;   // always < 3000
    const int r1 = r0 + 8;                           // may be >= 3000 in last block
    const int rB = (r1 < TT) ? r1 : (TT - 1);

    // K stride 36, V stride 40, mini-P stride 12: conflict-free patterns
    __shared__ __align__(16) float Ks[2][64 * 36];
    __shared__ __align__(16) float Vs[2][64 * 40];
    __shared__ __align__(16) float Ps[4][16 * 12];

    const float* Qh = Q  + (size_t)head * TT * DD;
    const float* Kh = Kg + (size_t)head * TT * DD;
    const float* Vh = Vg + (size_t)head * TT * DD;

    // ---- Q fragments, pre-scaled, hi/lo tf32 split (once) ----
    uint32_t qhf[4][4], qlf[4][4];
    #pragma unroll
    for (int c = 0; c < 4; ++c) {
        int col = c * 8 + tg;
        float v[4];
        v[0] = Qh[(size_t)r0 * DD + col]     * QSCALE;
        v[1] = Qh[(size_t)rB * DD + col]     * QSCALE;
        v[2] = Qh[(size_t)r0 * DD + col + 4] * QSCALE;
        v[3] = Qh[(size_t)rB * DD + col + 4] * QSCALE;
        #pragma unroll
        for (int i = 0; i < 4; ++i) {
            qhf[c][i] = tf32r(v[i]);
            qlf[c][i] = tf32r(v[i] - asf(qhf[c][i]));
        }
    }

    auto load_tile = [&](int tile, int buf) {
        int s0 = tile * 64;
        #pragma unroll
        for (int k = 0; k < 4; ++k) {
            int idx = tid + k * 128;             // 512 chunks: 64 rows x 8
            int s = idx >> 3, dc = (idx & 7) * 4;
            int sg = s0 + s;
            if (sg < TT) {
                cp16(&Ks[buf][s * 36 + dc], Kh + (size_t)sg * DD + dc);
                cp16(&Vs[buf][s * 40 + dc], Vh + (size_t)sg * DD + dc);
            } else {
                float4 z = make_float4(0.f, 0.f, 0.f, 0.f);
                *(float4*)&Ks[buf][s * 36 + dc] = z;
                *(float4*)&Vs[buf][s * 40 + dc] = z;
            }
        }
        asm volatile("cp.async.commit_group;" ::: "memory");
    };

    load_tile(0, 0);

    float o[4][4];
    #pragma unroll
    for (int i = 0; i < 4; ++i)
        #pragma unroll
        for (int j = 0; j < 4; ++j) o[i][j] = 0.f;
    float lr0 = 0.f, lr1 = 0.f;

    const unsigned* mbase = Mb + (size_t)n * MW * TT;
    float* Pw = &Ps[wid][0];

    for (int tile = 0; tile < 47; ++tile) {
        const int buf = tile & 1;
        if (tile + 1 < 47) {
            load_tile(tile + 1, buf ^ 1);
            asm volatile("cp.async.wait_group 1;" ::: "memory");
        } else {
            asm volatile("cp.async.wait_group 0;" ::: "memory");
        }
        __syncthreads();

        // mask words for this tile (BC=64 = exactly 2 words, tile-aligned)
        unsigned mw00 = mbase[(size_t)(2 * tile)     * TT + r0];
        unsigned mw01 = mbase[(size_t)(2 * tile + 1) * TT + r0];
        unsigned mw10 = mbase[(size_t)(2 * tile)     * TT + rB];
        unsigned mw11 = mbase[(size_t)(2 * tile + 1) * TT + rB];

        const float* Kb = &Ks[buf][0];
        const float* Vb = &Vs[buf][0];

        #pragma unroll 2
        for (int j = 0; j < 8; ++j) {
            // ---- QK^T for s-cols [j*8, j*8+8): 3xTF32 over 4 k-chunks ----
            float c0 = 0.f, c1 = 0.f, c2 = 0.f, c3 = 0.f;
            #pragma unroll
            for (int cc = 0; cc < 4; ++cc) {
                float b0r = Kb[(j * 8 + g) * 36 + cc * 8 + tg];
                float b1r = Kb[(j * 8 + g) * 36 + cc * 8 + tg + 4];
                uint32_t bh0 = tf32r(b0r), bh1 = tf32r(b1r);
                uint32_t bl0 = tf32r(b0r - asf(bh0)), bl1 = tf32r(b1r - asf(bh1));
                mma_tf32(c0, c1, c2, c3, qhf[cc][0], qhf[cc][1], qhf[cc][2], qhf[cc][3], bh0, bh1);
                mma_tf32(c0, c1, c2, c3, qlf[cc][0], qlf[cc][1], qlf[cc][2], qlf[cc][3], bh0, bh1);
                mma_tf32(c0, c1, c2, c3, qhf[cc][0], qhf[cc][1], qhf[cc][2], qhf[cc][3], bl0, bl1);
            }

            // ---- masked exp (no-max: scores bounded) ----
            unsigned m0 = (j & 4) ? mw01 : mw00;
            unsigned m1 = (j & 4) ? mw11 : mw10;
            int sh = (j * 8 + 2 * tg) & 31;
            float p0 = ((m0 >> sh)       & 1u) ? ex2f(c0) : 0.f;
            float p1 = ((m0 >> (sh + 1)) & 1u) ? ex2f(c1) : 0.f;
            float p2 = ((m1 >> sh)       & 1u) ? ex2f(c2) : 0.f;
            float p3 = ((m1 >> (sh + 1)) & 1u) ? ex2f(c3) : 0.f;
            lr0 += p0 + p1;
            lr1 += p2 + p3;

            // ---- redistribute P (C-layout -> A-layout), hi-only ----
            *(float2*)&Pw[g * 12 + 2 * tg]       = make_float2(p0, p1);
            *(float2*)&Pw[(g + 8) * 12 + 2 * tg] = make_float2(p2, p3);
            __syncwarp();
            uint32_t ah0 = tf32r(Pw[g * 12 + tg]);
            uint32_t ah1 = tf32r(Pw[(g + 8) * 12 + tg]);
            uint32_t ah2 = tf32r(Pw[g * 12 + tg + 4]);
            uint32_t ah3 = tf32r(Pw[(g + 8) * 12 + tg + 4]);

            // ---- PV: O[16x32] += tf32(P) * tf32(V), single term ----
            #pragma unroll
            for (int nt = 0; nt < 4; ++nt) {
                uint32_t vh0 = tf32r(Vb[(j * 8 + tg) * 40 + nt * 8 + g]);
                uint32_t vh1 = tf32r(Vb[(j * 8 + tg + 4) * 40 + nt * 8 + g]);
                mma_tf32(o[nt][0], o[nt][1], o[nt][2], o[nt][3], ah0, ah1, ah2, ah3, vh0, vh1);
            }
            __syncwarp();
        }
        __syncthreads();   // protect K/V buffers before next prefetch overwrites
    }

    // ---- row sums: reduce over the 4 threads sharing each row ----
    lr0 += __shfl_xor_sync(0xFFFFFFFFu, lr0, 1);
    lr0 += __shfl_xor_sync(0xFFFFFFFFu, lr0, 2);
    lr1 += __shfl_xor_sync(0xFFFFFFFFu, lr1, 1);
    lr1 += __shfl_xor_sync(0xFFFFFFFFu, lr1, 2);
    float inv0 = (lr0 > 0.f) ? 1.f / lr0 : 0.f;   // all-masked row -> 0
    float inv1 = (lr1 > 0.f) ? 1.f / lr1 : 0.f;

    float* Oh = O + (size_t)head * TT * DD;
    #pragma unroll
    for (int nt = 0; nt < 4; ++nt) {
        int d0 = nt * 8 + 2 * tg;
        *(float2*)&Oh[(size_t)r0 * DD + d0] =
            make_float2(o[nt][0] * inv0, o[nt][1] * inv0);
        if (r1 < TT)
            *(float2*)&Oh[(size_t)r1 * DD + d0] =
                make_float2(o[nt][2] * inv1, o[nt][3] * inv1);
    }
}

// ============================================================================
// 3) Merge: out = concat_heads(m) @ W_merge + b_merge
//    grid (4, 94, 2) block 256.  f32x2 inner product.
// ============================================================================
__global__ void merge_kernel(const float* __restrict__ W,
                             const float* __restrict__ bias,
                             float* __restrict__ out)
{
    const float* A = blockIdx.z ? g_m1 : g_m0;
    float* o = out + (size_t)blockIdx.z * MROW * CC;

    __shared__ float As[16][68];
    __shared__ float Bs[16][64];

    const int tid = threadIdx.x;
    const int tx = tid & 15, ty = tid >> 4;
    const int bm = blockIdx.y * 64, bn = blockIdx.x * 64;

    const int arow = tid >> 2, akc = (tid & 3) * 4;
    const int brow = tid >> 4, bnc = (tid & 15) * 4;

    float2 c2[4][2];
    #pragma unroll
    for (int i = 0; i < 4; ++i) { c2[i][0] = make_float2(0.f,0.f); c2[i][1] = make_float2(0.f,0.f); }

    for (int kt = 0; kt < HH; kt += 16) {
        int gr = bm + arow;
        int gk = kt + akc;                    // hidden index = f*32 + d
        float4 av = make_float4(0.f, 0.f, 0.f, 0.f);
        if (gr < MROW) {
            int n = gr / TT, t = gr % TT;
            int f = gk >> 5, d = gk & 31;
            av = *(const float4*)(A + ((size_t)(n * FCH + f) * TT + t) * DD + d);
        }
        As[akc + 0][arow] = av.x;
        As[akc + 1][arow] = av.y;
        As[akc + 2][arow] = av.z;
        As[akc + 3][arow] = av.w;
        *(float4*)&Bs[brow][bnc] =
            *(const float4*)(W + (size_t)(kt + brow) * CC + bn + bnc);
        __syncthreads();
        #pragma unroll
        for (int k = 0; k < 16; ++k) {
            float4 a  = *(float4*)&As[k][ty * 4];
            float4 bv = *(float4*)&Bs[k][tx * 4];
            float2 b01 = make_float2(bv.x, bv.y), b23 = make_float2(bv.z, bv.w);
            c2[0][0] = ffma2(make_float2(a.x,a.x), b01, c2[0][0]);
            c2[0][1] = ffma2(make_float2(a.x,a.x), b23, c2[0][1]);
            c2[1][0] = ffma2(make_float2(a.y,a.y), b01, c2[1][0]);
            c2[1][1] = ffma2(make_float2(a.y,a.y), b23, c2[1][1]);
            c2[2][0] = ffma2(make_float2(a.z,a.z), b01, c2[2][0]);
            c2[2][1] = ffma2(make_float2(a.z,a.z), b23, c2[2][1]);
            c2[3][0] = ffma2(make_float2(a.w,a.w), b01, c2[3][0]);
            c2[3][1] = ffma2(make_float2(a.w,a.w), b23, c2[3][1]);
        }
        __syncthreads();
    }

    #pragma unroll
    for (int i = 0; i < 4; ++i) {
        int gr = bm + ty * 4 + i;
        if (gr >= MROW) continue;
        float cv[4] = { c2[i][0].x, c2[i][0].y, c2[i][1].x, c2[i][1].y };
        #pragma unroll
        for (int j = 0; j < 4; ++j) {
            int gc = bn + tx * 4 + j;
            o[(size_t)gr * CC + gc] = cv[j] + bias[gc];
        }
    }
}

// ============================================================================
// launch
// ============================================================================
extern "C" void kernel_launch(void* const* d_in, const int* in_sizes, int n_in,
                              void* d_out, int out_size)
{
    const float* x0   = (const float*)d_in[0];
    const float* x1   = (const float*)d_in[1];
    const void*  mask = (const void*)d_in[2];
    const float* Wp   = (const float*)d_in[3];
    const float* bp   = (const float*)d_in[4];
    const float* Wm   = (const float*)d_in[5];
    const float* bmg  = (const float*)d_in[6];
    float* out = (float*)d_out;

    // 0) mask dtype detect + bit-pack both orientations (word-major)
    detect_kernel<<<1, 256>>>((const unsigned*)mask);
    pack_kernel<<<dim3(94, 94, 2), dim3(32, 32)>>>(mask);

    // 1) projection + head split (both tensors)
    proj_kernel<<<dim3(8, 94, 2), 256>>>(x0, x1, Wp, bp);

    // 2) bidirectional flash attention on tensor cores
    flashmma_kernel<<<dim3(47, NF, 2), 128>>>();

    // 3) merge heads + output projection (m0 -> first half, m1 -> second)
    merge_kernel<<<dim3(4, 94, 2), 256>>>(Wm, bmg, out);
}

// round 13
// speedup vs baseline: 2.1052x; 1.3786x over previous
#include <cuda_runtime.h>
#include <stdint.h>
#include <math.h>

// Problem constants
#define NB   2
#define TT   3000
#define CC   256
#define HH   256
#define FCH  8
#define DD   32
#define NF   (NB*FCH)          // 16 (n, head) pairs
#define MROW (NB*TT)           // 6000 combined GEMM rows
#define MW   96                // packed words per mask row (94 used)
#define QSCALE (0.17677669529663687f * 1.4426950408889634f)  // 1/sqrt(32)*log2(e)

// ---------------- scratch (static device globals: no allocations) ----------
__device__ float    g_q0[NF*TT*DD];
__device__ float    g_v0[NF*TT*DD];
__device__ float    g_q1[NF*TT*DD];
__device__ float    g_v1[NF*TT*DD];
__device__ float    g_m0[NF*TT*DD];
__device__ float    g_m1[NF*TT*DD];
// word-major packed masks: [n][word][row]
__device__ unsigned g_mb0[(size_t)NB*MW*TT];
__device__ unsigned g_mb1[(size_t)NB*MW*TT];
__device__ unsigned g_mflags;                  // bit0=f32 seen, bit1=bytepack seen, bit2=bf16 seen

// ---------------- helpers --------------------------------------------------
__device__ __forceinline__ float asf(uint32_t u) { return __uint_as_float(u); }
__device__ __forceinline__ uint32_t fui(float f) { return __float_as_uint(f); }

__device__ __forceinline__ uint32_t tf32r(float x) {
    uint32_t u;
    asm("cvt.rna.tf32.f32 %0, %1;" : "=r"(u) : "f"(x));
    return u;
}
__device__ __forceinline__ float tf32f(float x) { return asf(tf32r(x)); }

__device__ __forceinline__ float ex2f(float x) {
    float y;
    asm("ex2.approx.ftz.f32 %0, %1;" : "=f"(y) : "f"(x));
    return y;
}

__device__ __forceinline__ void cp16(void* sdst, const void* gsrc) {
    unsigned d = (unsigned)__cvta_generic_to_shared(sdst);
    asm volatile("cp.async.cg.shared.global [%0], [%1], 16;" :: "r"(d), "l"(gsrc));
}

__device__ __forceinline__ float2 ffma2(float2 a, float2 b, float2 c) {
    unsigned long long ua = *reinterpret_cast<unsigned long long*>(&a);
    unsigned long long ub = *reinterpret_cast<unsigned long long*>(&b);
    unsigned long long uc = *reinterpret_cast<unsigned long long*>(&c);
    unsigned long long ud;
    asm("fma.rn.f32x2 %0, %1, %2, %3;" : "=l"(ud) : "l"(ua), "l"(ub), "l"(uc));
    return *reinterpret_cast<float2*>(&ud);
}

// m16n8k8 tf32 mma: D += A*B  (fp32 accum)
__device__ __forceinline__ void mma_tf32(float& d0, float& d1, float& d2, float& d3,
                                         uint32_t a0, uint32_t a1, uint32_t a2, uint32_t a3,
                                         uint32_t b0, uint32_t b1) {
    asm("mma.sync.aligned.m16n8k8.row.col.f32.tf32.tf32.f32 "
        "{%0,%1,%2,%3},{%4,%5,%6,%7},{%8,%9},{%0,%1,%2,%3};"
        : "+f"(d0), "+f"(d1), "+f"(d2), "+f"(d3)
        : "r"(a0), "r"(a1), "r"(a2), "r"(a3), "r"(b0), "r"(b1));
}

// ============================================================================
// 0) Mask dtype detection, parallel. mzero resets flags (graph-deterministic),
//    detect scans 1MB with 64 blocks, pack derives kind from flags.
// ============================================================================
__global__ void mzero_kernel() { g_mflags = 0u; }

__global__ void detect_kernel(const unsigned* __restrict__ m)
{
    int i0 = (blockIdx.x * 256 + threadIdx.x) * 16;   // 64*256*16 = 262144 words
    unsigned fl = 0;
    #pragma unroll
    for (int k = 0; k < 16; ++k) {
        unsigned w = m[i0 + k];
        if (w == 0x3F803F80u || w == 0x00003F80u) fl |= 4u;
        else if (w == 0x3F800000u) fl |= 1u;
        else if (w > 1u) fl |= 2u;
    }
    fl |= __shfl_xor_sync(0xFFFFFFFFu, fl, 16);
    fl |= __shfl_xor_sync(0xFFFFFFFFu, fl, 8);
    fl |= __shfl_xor_sync(0xFFFFFFFFu, fl, 4);
    fl |= __shfl_xor_sync(0xFFFFFFFFu, fl, 2);
    fl |= __shfl_xor_sync(0xFFFFFFFFu, fl, 1);
    if ((threadIdx.x & 31) == 0 && fl) atomicOr(&g_mflags, fl);
}

// ============================================================================
// 0b) Pack mask into word-major bit arrays for both orientations.
//     grid (94, 94, 2), block (32, 32).
// ============================================================================
__global__ void pack_kernel(const void* __restrict__ m)
{
    __shared__ uint8_t tile[32][33];
    unsigned fl = g_mflags;
    const int kind = (fl & 4u) ? 3 : ((fl & 1u) ? 2 : ((fl & 2u) ? 0 : 1));
    const int n  = blockIdx.z;
    const int l0 = blockIdx.y * 32, s0 = blockIdx.x * 32;
    const int tx = threadIdx.x, ty = threadIdx.y;
    const int l = l0 + ty, s = s0 + tx;

    bool val = false;
    if (l < TT && s < TT) {
        size_t idx = ((size_t)n * TT + l) * TT + s;
        if      (kind == 0) val = ((const uint8_t*)m)[idx] != 0;
        else if (kind == 1) val = ((const int*)m)[idx] != 0;
        else if (kind == 2) val = ((const float*)m)[idx] != 0.0f;
        else                val = ((const unsigned short*)m)[idx] != 0;
    }

    unsigned w0 = __ballot_sync(0xFFFFFFFFu, val);
    if (tx == 0 && l < TT)
        g_mb0[((size_t)n * MW + blockIdx.x) * TT + l] = w0;

    tile[ty][tx] = val ? 1 : 0;
    __syncthreads();

    bool valT = tile[tx][ty] != 0;
    unsigned w1 = __ballot_sync(0xFFFFFFFFu, valT);
    if (tx == 0 && (s0 + ty) < TT)
        g_mb1[((size_t)n * MW + blockIdx.y) * TT + s0 + ty] = w1;
}

// ============================================================================
// 1) Projection: p = x @ W_proj + b_proj -> per-head q/v layout
//    grid (8, 94, 2) block 256.  f32x2 inner product.
// ============================================================================
__global__ void proj_kernel(const float* __restrict__ x0,
                            const float* __restrict__ x1,
                            const float* __restrict__ W,
                            const float* __restrict__ bias)
{
    const float* x  = blockIdx.z ? x1 : x0;
    float*       qh = blockIdx.z ? g_q1 : g_q0;
    float*       vh = blockIdx.z ? g_v1 : g_v0;

    __shared__ float As[16][68];
    __shared__ float Bs[16][64];

    const int tid = threadIdx.x;
    const int tx = tid & 15, ty = tid >> 4;
    const int bm = blockIdx.y * 64, bn = blockIdx.x * 64;

    const int arow = tid >> 2, akc = (tid & 3) * 4;
    const int brow = tid >> 4, bnc = (tid & 15) * 4;

    float2 c2[4][2];
    #pragma unroll
    for (int i = 0; i < 4; ++i) { c2[i][0] = make_float2(0.f,0.f); c2[i][1] = make_float2(0.f,0.f); }

    for (int kt = 0; kt < CC; kt += 16) {
        int gr = bm + arow;
        float4 av = make_float4(0.f, 0.f, 0.f, 0.f);
        if (gr < MROW) av = *(const float4*)(x + (size_t)gr * CC + kt + akc);
        As[akc + 0][arow] = av.x;
        As[akc + 1][arow] = av.y;
        As[akc + 2][arow] = av.z;
        As[akc + 3][arow] = av.w;
        *(float4*)&Bs[brow][bnc] =
            *(const float4*)(W + (size_t)(kt + brow) * (2 * HH) + bn + bnc);
        __syncthreads();
        #pragma unroll
        for (int k = 0; k < 16; ++k) {
            float4 a  = *(float4*)&As[k][ty * 4];
            float4 bv = *(float4*)&Bs[k][tx * 4];
            float2 b01 = make_float2(bv.x, bv.y), b23 = make_float2(bv.z, bv.w);
            c2[0][0] = ffma2(make_float2(a.x,a.x), b01, c2[0][0]);
            c2[0][1] = ffma2(make_float2(a.x,a.x), b23, c2[0][1]);
            c2[1][0] = ffma2(make_float2(a.y,a.y), b01, c2[1][0]);
            c2[1][1] = ffma2(make_float2(a.y,a.y), b23, c2[1][1]);
            c2[2][0] = ffma2(make_float2(a.z,a.z), b01, c2[2][0]);
            c2[2][1] = ffma2(make_float2(a.z,a.z), b23, c2[2][1]);
            c2[3][0] = ffma2(make_float2(a.w,a.w), b01, c2[3][0]);
            c2[3][1] = ffma2(make_float2(a.w,a.w), b23, c2[3][1]);
        }
        __syncthreads();
    }

    #pragma unroll
    for (int i = 0; i < 4; ++i) {
        int gr = bm + ty * 4 + i;
        if (gr >= MROW) continue;
        int n = gr / TT, t = gr % TT;
        float cv[4] = { c2[i][0].x, c2[i][0].y, c2[i][1].x, c2[i][1].y };
        #pragma unroll
        for (int j = 0; j < 4; ++j) {
            int gc = bn + tx * 4 + j;
            float v = cv[j] + bias[gc];
            int cc = gc & 255;
            int f = cc >> 5, d = cc & 31;
            float* dst = (gc < HH) ? qh : vh;
            dst[((size_t)(n * FCH + f) * TT + t) * DD + d] = v;
        }
    }
}

// ============================================================================
// 2) Flash attention on tensor cores.
//    K/V tiles tf32-converted IN PLACE once per block after cp.async arrival.
//    QK: 2-term (Qh*Kh + Ql*Kh).  PV: 1-term tf32(P)*tf32(V).  No-max softmax.
//    Block = 4 warps; 16 q-rows/warp (BR=64), BC=64 per tile, 47 tiles.
//    grid (47, 16, 2) block 128.
// ============================================================================
__global__ void __launch_bounds__(128)
flashmma_kernel()
{
    const int dir  = blockIdx.z;
    const float*    Q  = dir ? g_q1 : g_q0;
    const float*    Kg = dir ? g_q0 : g_q1;
    const float*    Vg = dir ? g_v0 : g_v1;
    const unsigned* Mb = dir ? g_mb1 : g_mb0;
    float*          O  = dir ? g_m1 : g_m0;

    const int head = blockIdx.y;          // 0..15
    const int n    = head >> 3;
    const int tid  = threadIdx.x;
    const int wid  = tid >> 5;
    const int lane = tid & 31;
    const int g    = lane >> 2;           // groupID (row within 8)
    const int tg   = lane & 3;            // thread-in-group

    const int r0 = blockIdx.x * 64 + wid * 16 + g;   // always < 3000
    const int r1 = r0 + 8;                           // may be >= 3000 in last block
    const int rB = (r1 < TT) ? r1 : (TT - 1);

    // K stride 36, V stride 40, mini-P stride 12: conflict-free patterns
    __shared__ __align__(16) float Ks[2][64 * 36];
    __shared__ __align__(16) float Vs[2][64 * 40];
    __shared__ __align__(16) float Ps[4][16 * 12];

    const float* Qh = Q  + (size_t)head * TT * DD;
    const float* Kh = Kg + (size_t)head * TT * DD;
    const float* Vh = Vg + (size_t)head * TT * DD;

    // ---- Q fragments, pre-scaled, hi/lo tf32 split (once) ----
    uint32_t qhf[4][4], qlf[4][4];
    #pragma unroll
    for (int c = 0; c < 4; ++c) {
        int col = c * 8 + tg;
        float v[4];
        v[0] = Qh[(size_t)r0 * DD + col]     * QSCALE;
        v[1] = Qh[(size_t)rB * DD + col]     * QSCALE;
        v[2] = Qh[(size_t)r0 * DD + col + 4] * QSCALE;
        v[3] = Qh[(size_t)rB * DD + col + 4] * QSCALE;
        #pragma unroll
        for (int i = 0; i < 4; ++i) {
            qhf[c][i] = tf32r(v[i]);
            qlf[c][i] = tf32r(v[i] - asf(qhf[c][i]));
        }
    }

    auto load_tile = [&](int tile, int buf) {
        int s0 = tile * 64;
        #pragma unroll
        for (int k = 0; k < 4; ++k) {
            int idx = tid + k * 128;             // 512 chunks: 64 rows x 8
            int s = idx >> 3, dc = (idx & 7) * 4;
            int sg = s0 + s;
            if (sg < TT) {
                cp16(&Ks[buf][s * 36 + dc], Kh + (size_t)sg * DD + dc);
                cp16(&Vs[buf][s * 40 + dc], Vh + (size_t)sg * DD + dc);
            } else {
                float4 z = make_float4(0.f, 0.f, 0.f, 0.f);
                *(float4*)&Ks[buf][s * 36 + dc] = z;
                *(float4*)&Vs[buf][s * 40 + dc] = z;
            }
        }
        asm volatile("cp.async.commit_group;" ::: "memory");
    };

    load_tile(0, 0);

    float o[4][4];
    #pragma unroll
    for (int i = 0; i < 4; ++i)
        #pragma unroll
        for (int j = 0; j < 4; ++j) o[i][j] = 0.f;
    float lr0 = 0.f, lr1 = 0.f;

    const unsigned* mbase = Mb + (size_t)n * MW * TT;
    float* Pw = &Ps[wid][0];

    for (int tile = 0; tile < 47; ++tile) {
        const int buf = tile & 1;
        if (tile + 1 < 47) {
            load_tile(tile + 1, buf ^ 1);
            asm volatile("cp.async.wait_group 1;" ::: "memory");
        } else {
            asm volatile("cp.async.wait_group 0;" ::: "memory");
        }
        __syncthreads();

        // ---- cooperative in-place tf32 conversion (once per block) ----
        {
            float4* kp = (float4*)&Ks[buf][0];   // 64*9 = 576 float4 (incl. pad)
            for (int i = tid; i < 576; i += 128) {
                float4 v = kp[i];
                v.x = tf32f(v.x); v.y = tf32f(v.y);
                v.z = tf32f(v.z); v.w = tf32f(v.w);
                kp[i] = v;
            }
            float4* vp = (float4*)&Vs[buf][0];   // 64*10 = 640 float4 (incl. pad)
            for (int i = tid; i < 640; i += 128) {
                float4 v = vp[i];
                v.x = tf32f(v.x); v.y = tf32f(v.y);
                v.z = tf32f(v.z); v.w = tf32f(v.w);
                vp[i] = v;
            }
        }
        __syncthreads();

        // mask words for this tile (BC=64 = exactly 2 words, tile-aligned)
        unsigned mw00 = mbase[(size_t)(2 * tile)     * TT + r0];
        unsigned mw01 = mbase[(size_t)(2 * tile + 1) * TT + r0];
        unsigned mw10 = mbase[(size_t)(2 * tile)     * TT + rB];
        unsigned mw11 = mbase[(size_t)(2 * tile + 1) * TT + rB];

        const float* Kb = &Ks[buf][0];
        const float* Vb = &Vs[buf][0];

        #pragma unroll 2
        for (int j = 0; j < 8; ++j) {
            // ---- QK^T: 2-term 3xTF32 (K pre-rounded in smem) ----
            float c0 = 0.f, c1 = 0.f, c2 = 0.f, c3 = 0.f;
            #pragma unroll
            for (int cc = 0; cc < 4; ++cc) {
                uint32_t bh0 = fui(Kb[(j * 8 + g) * 36 + cc * 8 + tg]);
                uint32_t bh1 = fui(Kb[(j * 8 + g) * 36 + cc * 8 + tg + 4]);
                mma_tf32(c0, c1, c2, c3, qhf[cc][0], qhf[cc][1], qhf[cc][2], qhf[cc][3], bh0, bh1);
                mma_tf32(c0, c1, c2, c3, qlf[cc][0], qlf[cc][1], qlf[cc][2], qlf[cc][3], bh0, bh1);
            }

            // ---- masked exp (no-max: scores bounded) ----
            unsigned m0 = (j & 4) ? mw01 : mw00;
            unsigned m1 = (j & 4) ? mw11 : mw10;
            int sh = (j * 8 + 2 * tg) & 31;
            float p0 = ((m0 >> sh)       & 1u) ? ex2f(c0) : 0.f;
            float p1 = ((m0 >> (sh + 1)) & 1u) ? ex2f(c1) : 0.f;
            float p2 = ((m1 >> sh)       & 1u) ? ex2f(c2) : 0.f;
            float p3 = ((m1 >> (sh + 1)) & 1u) ? ex2f(c3) : 0.f;
            lr0 += p0 + p1;
            lr1 += p2 + p3;

            // ---- redistribute P (C-layout -> A-layout), tf32-rounded ----
            *(float2*)&Pw[g * 12 + 2 * tg]       = make_float2(p0, p1);
            *(float2*)&Pw[(g + 8) * 12 + 2 * tg] = make_float2(p2, p3);
            __syncwarp();
            uint32_t ah0 = tf32r(Pw[g * 12 + tg]);
            uint32_t ah1 = tf32r(Pw[(g + 8) * 12 + tg]);
            uint32_t ah2 = tf32r(Pw[g * 12 + tg + 4]);
            uint32_t ah3 = tf32r(Pw[(g + 8) * 12 + tg + 4]);

            // ---- PV: O[16x32] += P * V (V pre-rounded in smem) ----
            #pragma unroll
            for (int nt = 0; nt < 4; ++nt) {
                uint32_t vh0 = fui(Vb[(j * 8 + tg) * 40 + nt * 8 + g]);
                uint32_t vh1 = fui(Vb[(j * 8 + tg + 4) * 40 + nt * 8 + g]);
                mma_tf32(o[nt][0], o[nt][1], o[nt][2], o[nt][3], ah0, ah1, ah2, ah3, vh0, vh1);
            }
            __syncwarp();
        }
        __syncthreads();   // all warps done with buf before it is overwritten
    }

    // ---- row sums: reduce over the 4 threads sharing each row ----
    lr0 += __shfl_xor_sync(0xFFFFFFFFu, lr0, 1);
    lr0 += __shfl_xor_sync(0xFFFFFFFFu, lr0, 2);
    lr1 += __shfl_xor_sync(0xFFFFFFFFu, lr1, 1);
    lr1 += __shfl_xor_sync(0xFFFFFFFFu, lr1, 2);
    float inv0 = (lr0 > 0.f) ? 1.f / lr0 : 0.f;   // all-masked row -> 0
    float inv1 = (lr1 > 0.f) ? 1.f / lr1 : 0.f;

    float* Oh = O + (size_t)head * TT * DD;
    #pragma unroll
    for (int nt = 0; nt < 4; ++nt) {
        int d0 = nt * 8 + 2 * tg;
        *(float2*)&Oh[(size_t)r0 * DD + d0] =
            make_float2(o[nt][0] * inv0, o[nt][1] * inv0);
        if (r1 < TT)
            *(float2*)&Oh[(size_t)r1 * DD + d0] =
                make_float2(o[nt][2] * inv1, o[nt][3] * inv1);
    }
}

// ============================================================================
// 3) Merge: out = concat_heads(m) @ W_merge + b_merge
//    grid (4, 94, 2) block 256.  f32x2 inner product.
// ============================================================================
__global__ void merge_kernel(const float* __restrict__ W,
                             const float* __restrict__ bias,
                             float* __restrict__ out)
{
    const float* A = blockIdx.z ? g_m1 : g_m0;
    float* o = out + (size_t)blockIdx.z * MROW * CC;

    __shared__ float As[16][68];
    __shared__ float Bs[16][64];

    const int tid = threadIdx.x;
    const int tx = tid & 15, ty = tid >> 4;
    const int bm = blockIdx.y * 64, bn = blockIdx.x * 64;

    const int arow = tid >> 2, akc = (tid & 3) * 4;
    const int brow = tid >> 4, bnc = (tid & 15) * 4;

    float2 c2[4][2];
    #pragma unroll
    for (int i = 0; i < 4; ++i) { c2[i][0] = make_float2(0.f,0.f); c2[i][1] = make_float2(0.f,0.f); }

    for (int kt = 0; kt < HH; kt += 16) {
        int gr = bm + arow;
        int gk = kt + akc;                    // hidden index = f*32 + d
        float4 av = make_float4(0.f, 0.f, 0.f, 0.f);
        if (gr < MROW) {
            int n = gr / TT, t = gr % TT;
            int f = gk >> 5, d = gk & 31;
            av = *(const float4*)(A + ((size_t)(n * FCH + f) * TT + t) * DD + d);
        }
        As[akc + 0][arow] = av.x;
        As[akc + 1][arow] = av.y;
        As[akc + 2][arow] = av.z;
        As[akc + 3][arow] = av.w;
        *(float4*)&Bs[brow][bnc] =
            *(const float4*)(W + (size_t)(kt + brow) * CC + bn + bnc);
        __syncthreads();
        #pragma unroll
        for (int k = 0; k < 16; ++k) {
            float4 a  = *(float4*)&As[k][ty * 4];
            float4 bv = *(float4*)&Bs[k][tx * 4];
            float2 b01 = make_float2(bv.x, bv.y), b23 = make_float2(bv.z, bv.w);
            c2[0][0] = ffma2(make_float2(a.x,a.x), b01, c2[0][0]);
            c2[0][1] = ffma2(make_float2(a.x,a.x), b23, c2[0][1]);
            c2[1][0] = ffma2(make_float2(a.y,a.y), b01, c2[1][0]);
            c2[1][1] = ffma2(make_float2(a.y,a.y), b23, c2[1][1]);
            c2[2][0] = ffma2(make_float2(a.z,a.z), b01, c2[2][0]);
            c2[2][1] = ffma2(make_float2(a.z,a.z), b23, c2[2][1]);
            c2[3][0] = ffma2(make_float2(a.w,a.w), b01, c2[3][0]);
            c2[3][1] = ffma2(make_float2(a.w,a.w), b23, c2[3][1]);
        }
        __syncthreads();
    }

    #pragma unroll
    for (int i = 0; i < 4; ++i) {
        int gr = bm + ty * 4 + i;
        if (gr >= MROW) continue;
        float cv[4] = { c2[i][0].x, c2[i][0].y, c2[i][1].x, c2[i][1].y };
        #pragma unroll
        for (int j = 0; j < 4; ++j) {
            int gc = bn + tx * 4 + j;
            o[(size_t)gr * CC + gc] = cv[j] + bias[gc];
        }
    }
}

// ============================================================================
// launch
// ============================================================================
extern "C" void kernel_launch(void* const* d_in, const int* in_sizes, int n_in,
                              void* d_out, int out_size)
{
    const float* x0   = (const float*)d_in[0];
    const float* x1   = (const float*)d_in[1];
    const void*  mask = (const void*)d_in[2];
    const float* Wp   = (const float*)d_in[3];
    const float* bp   = (const float*)d_in[4];
    const float* Wm   = (const float*)d_in[5];
    const float* bmg  = (const float*)d_in[6];
    float* out = (float*)d_out;

    // 0) mask dtype detect (parallel) + bit-pack both orientations
    mzero_kernel<<<1, 1>>>();
    detect_kernel<<<64, 256>>>((const unsigned*)mask);
    pack_kernel<<<dim3(94, 94, 2), dim3(32, 32)>>>(mask);

    // 1) projection + head split (both tensors)
    proj_kernel<<<dim3(8, 94, 2), 256>>>(x0, x1, Wp, bp);

    // 2) bidirectional flash attention on tensor cores
    flashmma_kernel<<<dim3(47, NF, 2), 128>>>();

    // 3) merge heads + output projection (m0 -> first half, m1 -> second)
    merge_kernel<<<dim3(4, 94, 2), 256>>>(Wm, bmg, out);
}

// round 15
// speedup vs baseline: 2.2938x; 1.0896x over previous
#include <cuda_runtime.h>
#include <stdint.h>
#include <math.h>

// Problem constants
#define NB   2
#define TT   3000
#define CC   256
#define HH   256
#define FCH  8
#define DD   32
#define NF   (NB*FCH)          // 16 (n, head) pairs
#define MROW (NB*TT)           // 6000 combined GEMM rows
#define MW   96                // packed words per mask row (94 used)
#define QSCALE (0.17677669529663687f * 1.4426950408889634f)  // 1/sqrt(32)*log2(e)

// ---------------- scratch (static device globals: no allocations) ----------
__device__ float    g_q0[NF*TT*DD];
__device__ float    g_v0[NF*TT*DD];
__device__ float    g_q1[NF*TT*DD];
__device__ float    g_v1[NF*TT*DD];
__device__ float    g_m0[NF*TT*DD];
__device__ float    g_m1[NF*TT*DD];
// word-major packed masks: [n][word][row]
__device__ unsigned g_mb0[(size_t)NB*MW*TT];
__device__ unsigned g_mb1[(size_t)NB*MW*TT];
__device__ unsigned g_mflags;                  // bit0=f32, bit1=bytepack, bit2=bf16

// ---------------- helpers --------------------------------------------------
__device__ __forceinline__ float asf(uint32_t u) { return __uint_as_float(u); }
__device__ __forceinline__ uint32_t fui(float f) { return __float_as_uint(f); }

__device__ __forceinline__ uint32_t tf32r(float x) {
    uint32_t u;
    asm("cvt.rna.tf32.f32 %0, %1;" : "=r"(u) : "f"(x));
    return u;
}
__device__ __forceinline__ float tf32f(float x) { return asf(tf32r(x)); }

__device__ __forceinline__ float ex2f(float x) {
    float y;
    asm("ex2.approx.ftz.f32 %0, %1;" : "=f"(y) : "f"(x));
    return y;
}

__device__ __forceinline__ void cp16(void* sdst, const void* gsrc) {
    unsigned d = (unsigned)__cvta_generic_to_shared(sdst);
    asm volatile("cp.async.cg.shared.global [%0], [%1], 16;" :: "r"(d), "l"(gsrc));
}

__device__ __forceinline__ float2 ffma2(float2 a, float2 b, float2 c) {
    unsigned long long ua = *reinterpret_cast<unsigned long long*>(&a);
    unsigned long long ub = *reinterpret_cast<unsigned long long*>(&b);
    unsigned long long uc = *reinterpret_cast<unsigned long long*>(&c);
    unsigned long long ud;
    asm("fma.rn.f32x2 %0, %1, %2, %3;" : "=l"(ud) : "l"(ua), "l"(ub), "l"(uc));
    return *reinterpret_cast<float2*>(&ud);
}

// m16n8k8 tf32 mma: D += A*B  (fp32 accum)
__device__ __forceinline__ void mma_tf32(float& d0, float& d1, float& d2, float& d3,
                                         uint32_t a0, uint32_t a1, uint32_t a2, uint32_t a3,
                                         uint32_t b0, uint32_t b1) {
    asm("mma.sync.aligned.m16n8k8.row.col.f32.tf32.tf32.f32 "
        "{%0,%1,%2,%3},{%4,%5,%6,%7},{%8,%9},{%0,%1,%2,%3};"
        : "+f"(d0), "+f"(d1), "+f"(d2), "+f"(d3)
        : "r"(a0), "r"(a1), "r"(a2), "r"(a3), "r"(b0), "r"(b1));
}

// ============================================================================
// 0) Mask dtype detection, parallel.
// ============================================================================
__global__ void mzero_kernel() { g_mflags = 0u; }

__global__ void detect_kernel(const unsigned* __restrict__ m)
{
    int i0 = (blockIdx.x * 256 + threadIdx.x) * 16;   // 64*256*16 = 262144 words
    unsigned fl = 0;
    #pragma unroll
    for (int k = 0; k < 16; ++k) {
        unsigned w = m[i0 + k];
        if (w == 0x3F803F80u || w == 0x00003F80u) fl |= 4u;
        else if (w == 0x3F800000u) fl |= 1u;
        else if (w > 1u) fl |= 2u;
    }
    fl |= __shfl_xor_sync(0xFFFFFFFFu, fl, 16);
    fl |= __shfl_xor_sync(0xFFFFFFFFu, fl, 8);
    fl |= __shfl_xor_sync(0xFFFFFFFFu, fl, 4);
    fl |= __shfl_xor_sync(0xFFFFFFFFu, fl, 2);
    fl |= __shfl_xor_sync(0xFFFFFFFFu, fl, 1);
    if ((threadIdx.x & 31) == 0 && fl) atomicOr(&g_mflags, fl);
}

// ============================================================================
// 0b) Pack mask into word-major bit arrays for both orientations.
//     grid (94, 94, 2), block (32, 32).
// ============================================================================
__global__ void pack_kernel(const void* __restrict__ m)
{
    __shared__ uint8_t tile[32][33];
    unsigned fl = g_mflags;
    const int kind = (fl & 4u) ? 3 : ((fl & 1u) ? 2 : ((fl & 2u) ? 0 : 1));
    const int n  = blockIdx.z;
    const int l0 = blockIdx.y * 32, s0 = blockIdx.x * 32;
    const int tx = threadIdx.x, ty = threadIdx.y;
    const int l = l0 + ty, s = s0 + tx;

    bool val = false;
    if (l < TT && s < TT) {
        size_t idx = ((size_t)n * TT + l) * TT + s;
        if      (kind == 0) val = ((const uint8_t*)m)[idx] != 0;
        else if (kind == 1) val = ((const int*)m)[idx] != 0;
        else if (kind == 2) val = ((const float*)m)[idx] != 0.0f;
        else                val = ((const unsigned short*)m)[idx] != 0;
    }

    unsigned w0 = __ballot_sync(0xFFFFFFFFu, val);
    if (tx == 0 && l < TT)
        g_mb0[((size_t)n * MW + blockIdx.x) * TT + l] = w0;

    tile[ty][tx] = val ? 1 : 0;
    __syncthreads();

    bool valT = tile[tx][ty] != 0;
    unsigned w1 = __ballot_sync(0xFFFFFFFFu, valT);
    if (tx == 0 && (s0 + ty) < TT)
        g_mb1[((size_t)n * MW + blockIdx.y) * TT + s0 + ty] = w1;
}

// ============================================================================
// 1) Projection: p = x @ W_proj + b_proj -> per-head q/v layout
//    128x64 block tile, 8x4 per thread.  grid (8, 47, 2) block 256.
// ============================================================================
__global__ void proj_kernel(const float* __restrict__ x0,
                            const float* __restrict__ x1,
                            const float* __restrict__ W,
                            const float* __restrict__ bias)
{
    const float* x  = blockIdx.z ? x1 : x0;
    float*       qh = blockIdx.z ? g_q1 : g_q0;
    float*       vh = blockIdx.z ? g_v1 : g_v0;

    __shared__ float As[16][132];   // [k][row], pad for bank spread
    __shared__ float Bs[16][64];

    const int tid = threadIdx.x;
    const int tx = tid & 15, ty = tid >> 4;
    const int bm = blockIdx.y * 128, bn = blockIdx.x * 64;

    const int arow = tid >> 1, akc = (tid & 1) * 8;   // 2 float4 per thread
    const int brow = tid >> 4, bnc = (tid & 15) * 4;

    float2 c2[8][2];
    #pragma unroll
    for (int i = 0; i < 8; ++i) { c2[i][0] = make_float2(0.f,0.f); c2[i][1] = make_float2(0.f,0.f); }

    for (int kt = 0; kt < CC; kt += 16) {
        int gr = bm + arow;
        float4 a0 = make_float4(0.f,0.f,0.f,0.f), a1 = a0;
        if (gr < MROW) {
            a0 = *(const float4*)(x + (size_t)gr * CC + kt + akc);
            a1 = *(const float4*)(x + (size_t)gr * CC + kt + akc + 4);
        }
        As[akc + 0][arow] = a0.x; As[akc + 1][arow] = a0.y;
        As[akc + 2][arow] = a0.z; As[akc + 3][arow] = a0.w;
        As[akc + 4][arow] = a1.x; As[akc + 5][arow] = a1.y;
        As[akc + 6][arow] = a1.z; As[akc + 7][arow] = a1.w;
        *(float4*)&Bs[brow][bnc] =
            *(const float4*)(W + (size_t)(kt + brow) * (2 * HH) + bn + bnc);
        __syncthreads();
        #pragma unroll
        for (int k = 0; k < 16; ++k) {
            float4 av0 = *(float4*)&As[k][ty * 8];
            float4 av1 = *(float4*)&As[k][ty * 8 + 4];
            float4 bv  = *(float4*)&Bs[k][tx * 4];
            float2 b01 = make_float2(bv.x, bv.y), b23 = make_float2(bv.z, bv.w);
            float a[8] = { av0.x, av0.y, av0.z, av0.w, av1.x, av1.y, av1.z, av1.w };
            #pragma unroll
            for (int i = 0; i < 8; ++i) {
                float2 aa = make_float2(a[i], a[i]);
                c2[i][0] = ffma2(aa, b01, c2[i][0]);
                c2[i][1] = ffma2(aa, b23, c2[i][1]);
            }
        }
        __syncthreads();
    }

    #pragma unroll
    for (int i = 0; i < 8; ++i) {
        int gr = bm + ty * 8 + i;
        if (gr >= MROW) continue;
        int n = gr / TT, t = gr % TT;
        float cv[4] = { c2[i][0].x, c2[i][0].y, c2[i][1].x, c2[i][1].y };
        #pragma unroll
        for (int j = 0; j < 4; ++j) {
            int gc = bn + tx * 4 + j;
            float v = cv[j] + bias[gc];
            int cc = gc & 255;
            int f = cc >> 5, d = cc & 31;
            float* dst = (gc < HH) ? qh : vh;
            dst[((size_t)(n * FCH + f) * TT + t) * DD + d] = v;
        }
    }
}

// ============================================================================
// 2) Flash attention on tensor cores.
//    K/V tiles tf32-converted IN PLACE once per block after cp.async arrival.
//    QK: 1-term tf32(Q)*tf32(K).  PV: 1-term tf32(P)*tf32(V).  No-max softmax.
//    Block = 4 warps; 16 q-rows/warp (BR=64), BC=64 per tile, 47 tiles.
//    grid (47, 16, 2) block 128.
// ============================================================================
__global__ void __launch_bounds__(128)
flashmma_kernel()
{
    const int dir  = blockIdx.z;
    const float*    Q  = dir ? g_q1 : g_q0;
    const float*    Kg = dir ? g_q0 : g_q1;
    const float*    Vg = dir ? g_v0 : g_v1;
    const unsigned* Mb = dir ? g_mb1 : g_mb0;
    float*          O  = dir ? g_m1 : g_m0;

    const int head = blockIdx.y;          // 0..15
    const int n    = head >> 3;
    const int tid  = threadIdx.x;
    const int wid  = tid >> 5;
    const int lane = tid & 31;
    const int g    = lane >> 2;           // groupID (row within 8)
    const int tg   = lane & 3;            // thread-in-group

    const int r0 = blockIdx.x * 64 + wid * 16 + g;   // always < 3000
    const int r1 = r0 + 8;                           // may be >= 3000 in last block
    const int rB = (r1 < TT) ? r1 : (TT - 1);

    // K stride 36, V stride 40, mini-P stride 12: conflict-free patterns
    __shared__ __align__(16) float Ks[2][64 * 36];
    __shared__ __align__(16) float Vs[2][64 * 40];
    __shared__ __align__(16) float Ps[4][16 * 12];

    const float* Qh = Q  + (size_t)head * TT * DD;
    const float* Kh = Kg + (size_t)head * TT * DD;
    const float* Vh = Vg + (size_t)head * TT * DD;

    // ---- Q fragments, pre-scaled, tf32-rounded (hi only) ----
    uint32_t qhf[4][4];
    #pragma unroll
    for (int c = 0; c < 4; ++c) {
        int col = c * 8 + tg;
        qhf[c][0] = tf32r(Qh[(size_t)r0 * DD + col]     * QSCALE);
        qhf[c][1] = tf32r(Qh[(size_t)rB * DD + col]     * QSCALE);
        qhf[c][2] = tf32r(Qh[(size_t)r0 * DD + col + 4] * QSCALE);
        qhf[c][3] = tf32r(Qh[(size_t)rB * DD + col + 4] * QSCALE);
    }

    auto load_tile = [&](int tile, int buf) {
        int s0 = tile * 64;
        #pragma unroll
        for (int k = 0; k < 4; ++k) {
            int idx = tid + k * 128;             // 512 chunks: 64 rows x 8
            int s = idx >> 3, dc = (idx & 7) * 4;
            int sg = s0 + s;
            if (sg < TT) {
                cp16(&Ks[buf][s * 36 + dc], Kh + (size_t)sg * DD + dc);
                cp16(&Vs[buf][s * 40 + dc], Vh + (size_t)sg * DD + dc);
            } else {
                float4 z = make_float4(0.f, 0.f, 0.f, 0.f);
                *(float4*)&Ks[buf][s * 36 + dc] = z;
                *(float4*)&Vs[buf][s * 40 + dc] = z;
            }
        }
        asm volatile("cp.async.commit_group;" ::: "memory");
    };

    load_tile(0, 0);

    float o[4][4];
    #pragma unroll
    for (int i = 0; i < 4; ++i)
        #pragma unroll
        for (int j = 0; j < 4; ++j) o[i][j] = 0.f;
    float lr0 = 0.f, lr1 = 0.f;

    const unsigned* mbase = Mb + (size_t)n * MW * TT;
    float* Pw = &Ps[wid][0];

    for (int tile = 0; tile < 47; ++tile) {
        const int buf = tile & 1;
        if (tile + 1 < 47) {
            load_tile(tile + 1, buf ^ 1);
            asm volatile("cp.async.wait_group 1;" ::: "memory");
        } else {
            asm volatile("cp.async.wait_group 0;" ::: "memory");
        }
        __syncthreads();

        // ---- cooperative in-place tf32 conversion (once per block) ----
        {
            float4* kp = (float4*)&Ks[buf][0];   // 576 float4 (incl. pad)
            for (int i = tid; i < 576; i += 128) {
                float4 v = kp[i];
                v.x = tf32f(v.x); v.y = tf32f(v.y);
                v.z = tf32f(v.z); v.w = tf32f(v.w);
                kp[i] = v;
            }
            float4* vp = (float4*)&Vs[buf][0];   // 640 float4 (incl. pad)
            for (int i = tid; i < 640; i += 128) {
                float4 v = vp[i];
                v.x = tf32f(v.x); v.y = tf32f(v.y);
                v.z = tf32f(v.z); v.w = tf32f(v.w);
                vp[i] = v;
            }
        }
        __syncthreads();

        // mask words for this tile (BC=64 = exactly 2 words, tile-aligned)
        unsigned mw00 = mbase[(size_t)(2 * tile)     * TT + r0];
        unsigned mw01 = mbase[(size_t)(2 * tile + 1) * TT + r0];
        unsigned mw10 = mbase[(size_t)(2 * tile)     * TT + rB];
        unsigned mw11 = mbase[(size_t)(2 * tile + 1) * TT + rB];

        const float* Kb = &Ks[buf][0];
        const float* Vb = &Vs[buf][0];

        #pragma unroll 2
        for (int j = 0; j < 8; ++j) {
            // ---- QK^T: 1-term (Q and K tf32-rounded) ----
            float c0 = 0.f, c1 = 0.f, c2 = 0.f, c3 = 0.f;
            #pragma unroll
            for (int cc = 0; cc < 4; ++cc) {
                uint32_t bh0 = fui(Kb[(j * 8 + g) * 36 + cc * 8 + tg]);
                uint32_t bh1 = fui(Kb[(j * 8 + g) * 36 + cc * 8 + tg + 4]);
                mma_tf32(c0, c1, c2, c3, qhf[cc][0], qhf[cc][1], qhf[cc][2], qhf[cc][3], bh0, bh1);
            }

            // ---- masked exp (no-max: scores bounded) ----
            unsigned m0 = (j & 4) ? mw01 : mw00;
            unsigned m1 = (j & 4) ? mw11 : mw10;
            int sh = (j * 8 + 2 * tg) & 31;
            float p0 = ((m0 >> sh)       & 1u) ? ex2f(c0) : 0.f;
            float p1 = ((m0 >> (sh + 1)) & 1u) ? ex2f(c1) : 0.f;
            float p2 = ((m1 >> sh)       & 1u) ? ex2f(c2) : 0.f;
            float p3 = ((m1 >> (sh + 1)) & 1u) ? ex2f(c3) : 0.f;
            lr0 += p0 + p1;
            lr1 += p2 + p3;

            // ---- redistribute P (C-layout -> A-layout), tf32-rounded ----
            *(float2*)&Pw[g * 12 + 2 * tg]       = make_float2(p0, p1);
            *(float2*)&Pw[(g + 8) * 12 + 2 * tg] = make_float2(p2, p3);
            __syncwarp();
            uint32_t ah0 = tf32r(Pw[g * 12 + tg]);
            uint32_t ah1 = tf32r(Pw[(g + 8) * 12 + tg]);
            uint32_t ah2 = tf32r(Pw[g * 12 + tg + 4]);
            uint32_t ah3 = tf32r(Pw[(g + 8) * 12 + tg + 4]);

            // ---- PV: O[16x32] += P * V (V pre-rounded in smem) ----
            #pragma unroll
            for (int nt = 0; nt < 4; ++nt) {
                uint32_t vh0 = fui(Vb[(j * 8 + tg) * 40 + nt * 8 + g]);
                uint32_t vh1 = fui(Vb[(j * 8 + tg + 4) * 40 + nt * 8 + g]);
                mma_tf32(o[nt][0], o[nt][1], o[nt][2], o[nt][3], ah0, ah1, ah2, ah3, vh0, vh1);
            }
            __syncwarp();
        }
        __syncthreads();   // all warps done with buf before it is overwritten
    }

    // ---- row sums: reduce over the 4 threads sharing each row ----
    lr0 += __shfl_xor_sync(0xFFFFFFFFu, lr0, 1);
    lr0 += __shfl_xor_sync(0xFFFFFFFFu, lr0, 2);
    lr1 += __shfl_xor_sync(0xFFFFFFFFu, lr1, 1);
    lr1 += __shfl_xor_sync(0xFFFFFFFFu, lr1, 2);
    float inv0 = (lr0 > 0.f) ? 1.f / lr0 : 0.f;   // all-masked row -> 0
    float inv1 = (lr1 > 0.f) ? 1.f / lr1 : 0.f;

    float* Oh = O + (size_t)head * TT * DD;
    #pragma unroll
    for (int nt = 0; nt < 4; ++nt) {
        int d0 = nt * 8 + 2 * tg;
        *(float2*)&Oh[(size_t)r0 * DD + d0] =
            make_float2(o[nt][0] * inv0, o[nt][1] * inv0);
        if (r1 < TT)
            *(float2*)&Oh[(size_t)r1 * DD + d0] =
                make_float2(o[nt][2] * inv1, o[nt][3] * inv1);
    }
}

// ============================================================================
// 3) Merge: out = concat_heads(m) @ W_merge + b_merge
//    128x64 block tile, 8x4 per thread.  grid (4, 47, 2) block 256.
// ============================================================================
__global__ void merge_kernel(const float* __restrict__ W,
                             const float* __restrict__ bias,
                             float* __restrict__ out)
{
    const float* A = blockIdx.z ? g_m1 : g_m0;
    float* o = out + (size_t)blockIdx.z * MROW * CC;

    __shared__ float As[16][132];
    __shared__ float Bs[16][64];

    const int tid = threadIdx.x;
    const int tx = tid & 15, ty = tid >> 4;
    const int bm = blockIdx.y * 128, bn = blockIdx.x * 64;

    const int arow = tid >> 1, akc = (tid & 1) * 8;
    const int brow = tid >> 4, bnc = (tid & 15) * 4;

    float2 c2[8][2];
    #pragma unroll
    for (int i = 0; i < 8; ++i) { c2[i][0] = make_float2(0.f,0.f); c2[i][1] = make_float2(0.f,0.f); }

    for (int kt = 0; kt < HH; kt += 16) {
        int gr = bm + arow;
        int gk = kt + akc;                    // hidden index = f*32 + d (8-aligned)
        float4 a0 = make_float4(0.f,0.f,0.f,0.f), a1 = a0;
        if (gr < MROW) {
            int n = gr / TT, t = gr % TT;
            int f = gk >> 5, d = gk & 31;
            const float* src = A + ((size_t)(n * FCH + f) * TT + t) * DD + d;
            a0 = *(const float4*)(src);
            a1 = *(const float4*)(src + 4);
        }
        As[akc + 0][arow] = a0.x; As[akc + 1][arow] = a0.y;
        As[akc + 2][arow] = a0.z; As[akc + 3][arow] = a0.w;
        As[akc + 4][arow] = a1.x; As[akc + 5][arow] = a1.y;
        As[akc + 6][arow] = a1.z; As[akc + 7][arow] = a1.w;
        *(float4*)&Bs[brow][bnc] =
            *(const float4*)(W + (size_t)(kt + brow) * CC + bn + bnc);
        __syncthreads();
        #pragma unroll
        for (int k = 0; k < 16; ++k) {
            float4 av0 = *(float4*)&As[k][ty * 8];
            float4 av1 = *(float4*)&As[k][ty * 8 + 4];
            float4 bv  = *(float4*)&Bs[k][tx * 4];
            float2 b01 = make_float2(bv.x, bv.y), b23 = make_float2(bv.z, bv.w);
            float a[8] = { av0.x, av0.y, av0.z, av0.w, av1.x, av1.y, av1.z, av1.w };
            #pragma unroll
            for (int i = 0; i < 8; ++i) {
                float2 aa = make_float2(a[i], a[i]);
                c2[i][0] = ffma2(aa, b01, c2[i][0]);
                c2[i][1] = ffma2(aa, b23, c2[i][1]);
            }
        }
        __syncthreads();
    }

    #pragma unroll
    for (int i = 0; i < 8; ++i) {
        int gr = bm + ty * 8 + i;
        if (gr >= MROW) continue;
        float cv[4] = { c2[i][0].x, c2[i][0].y, c2[i][1].x, c2[i][1].y };
        #pragma unroll
        for (int j = 0; j < 4; ++j) {
            int gc = bn + tx * 4 + j;
            o[(size_t)gr * CC + gc] = cv[j] + bias[gc];
        }
    }
}

// ============================================================================
// launch
// ============================================================================
extern "C" void kernel_launch(void* const* d_in, const int* in_sizes, int n_in,
                              void* d_out, int out_size)
{
    const float* x0   = (const float*)d_in[0];
    const float* x1   = (const float*)d_in[1];
    const void*  mask = (const void*)d_in[2];
    const float* Wp   = (const float*)d_in[3];
    const float* bp   = (const float*)d_in[4];
    const float* Wm   = (const float*)d_in[5];
    const float* bmg  = (const float*)d_in[6];
    float* out = (float*)d_out;

    // 0) mask dtype detect (parallel) + bit-pack both orientations
    mzero_kernel<<<1, 1>>>();
    detect_kernel<<<64, 256>>>((const unsigned*)mask);
    pack_kernel<<<dim3(94, 94, 2), dim3(32, 32)>>>(mask);

    // 1) projection + head split (both tensors)
    proj_kernel<<<dim3(8, 47, 2), 256>>>(x0, x1, Wp, bp);

    // 2) bidirectional flash attention on tensor cores
    flashmma_kernel<<<dim3(47, NF, 2), 128>>>();

    // 3) merge heads + output projection (m0 -> first half, m1 -> second)
    merge_kernel<<<dim3(4, 47, 2), 256>>>(Wm, bmg, out);
}

// round 17
// speedup vs baseline: 2.5993x; 1.1332x over previous
#include <cuda_runtime.h>
#include <stdint.h>
#include <math.h>

// Problem constants
#define NB   2
#define TT   3000
#define CC   256
#define HH   256
#define FCH  8
#define DD   32
#define NF   (NB*FCH)          // 16 (n, head) pairs
#define MROW (NB*TT)           // 6000 combined GEMM rows
#define MW   96                // packed words per mask row (94 used)
#define QSCALE (0.17677669529663687f * 1.4426950408889634f)  // 1/sqrt(32)*log2(e)

// ---------------- scratch (static device globals: no allocations) ----------
// q/v are stored TF32-PRE-ROUNDED by proj (consumed bit-exact by flash mma).
__device__ float    g_q0[NF*TT*DD];
__device__ float    g_v0[NF*TT*DD];
__device__ float    g_q1[NF*TT*DD];
__device__ float    g_v1[NF*TT*DD];
__device__ float    g_m0[NF*TT*DD];
__device__ float    g_m1[NF*TT*DD];
// word-major packed masks: [n][word][row]
__device__ unsigned g_mb0[(size_t)NB*MW*TT];
__device__ unsigned g_mb1[(size_t)NB*MW*TT];
__device__ unsigned g_mflags;                  // bit0=f32, bit1=bytepack, bit2=bf16

// ---------------- helpers --------------------------------------------------
__device__ __forceinline__ float asf(uint32_t u) { return __uint_as_float(u); }
__device__ __forceinline__ uint32_t fui(float f) { return __float_as_uint(f); }

__device__ __forceinline__ uint32_t tf32r(float x) {
    uint32_t u;
    asm("cvt.rna.tf32.f32 %0, %1;" : "=r"(u) : "f"(x));
    return u;
}
__device__ __forceinline__ float tf32f(float x) { return asf(tf32r(x)); }

__device__ __forceinline__ float ex2f(float x) {
    float y;
    asm("ex2.approx.ftz.f32 %0, %1;" : "=f"(y) : "f"(x));
    return y;
}

__device__ __forceinline__ void cp16(void* sdst, const void* gsrc) {
    unsigned d = (unsigned)__cvta_generic_to_shared(sdst);
    asm volatile("cp.async.cg.shared.global [%0], [%1], 16;" :: "r"(d), "l"(gsrc));
}

__device__ __forceinline__ float2 ffma2(float2 a, float2 b, float2 c) {
    unsigned long long ua = *reinterpret_cast<unsigned long long*>(&a);
    unsigned long long ub = *reinterpret_cast<unsigned long long*>(&b);
    unsigned long long uc = *reinterpret_cast<unsigned long long*>(&c);
    unsigned long long ud;
    asm("fma.rn.f32x2 %0, %1, %2, %3;" : "=l"(ud) : "l"(ua), "l"(ub), "l"(uc));
    return *reinterpret_cast<float2*>(&ud);
}

// m16n8k8 tf32 mma: D += A*B  (fp32 accum)
__device__ __forceinline__ void mma_tf32(float& d0, float& d1, float& d2, float& d3,
                                         uint32_t a0, uint32_t a1, uint32_t a2, uint32_t a3,
                                         uint32_t b0, uint32_t b1) {
    asm("mma.sync.aligned.m16n8k8.row.col.f32.tf32.tf32.f32 "
        "{%0,%1,%2,%3},{%4,%5,%6,%7},{%8,%9},{%0,%1,%2,%3};"
        : "+f"(d0), "+f"(d1), "+f"(d2), "+f"(d3)
        : "r"(a0), "r"(a1), "r"(a2), "r"(a3), "r"(b0), "r"(b1));
}

// ============================================================================
// 0) Mask dtype detection, parallel.
// ============================================================================
__global__ void mzero_kernel() { g_mflags = 0u; }

__global__ void detect_kernel(const unsigned* __restrict__ m)
{
    int i0 = (blockIdx.x * 256 + threadIdx.x) * 16;   // 64*256*16 = 262144 words
    unsigned fl = 0;
    #pragma unroll
    for (int k = 0; k < 16; ++k) {
        unsigned w = m[i0 + k];
        if (w == 0x3F803F80u || w == 0x00003F80u) fl |= 4u;
        else if (w == 0x3F800000u) fl |= 1u;
        else if (w > 1u) fl |= 2u;
    }
    fl |= __shfl_xor_sync(0xFFFFFFFFu, fl, 16);
    fl |= __shfl_xor_sync(0xFFFFFFFFu, fl, 8);
    fl |= __shfl_xor_sync(0xFFFFFFFFu, fl, 4);
    fl |= __shfl_xor_sync(0xFFFFFFFFu, fl, 2);
    fl |= __shfl_xor_sync(0xFFFFFFFFu, fl, 1);
    if ((threadIdx.x & 31) == 0 && fl) atomicOr(&g_mflags, fl);
}

// ============================================================================
// 0b) Pack mask into word-major bit arrays for both orientations.
//     grid (94, 94, 2), block (32, 32).
// ============================================================================
__global__ void pack_kernel(const void* __restrict__ m)
{
    __shared__ uint8_t tile[32][33];
    unsigned fl = g_mflags;
    const int kind = (fl & 4u) ? 3 : ((fl & 1u) ? 2 : ((fl & 2u) ? 0 : 1));
    const int n  = blockIdx.z;
    const int l0 = blockIdx.y * 32, s0 = blockIdx.x * 32;
    const int tx = threadIdx.x, ty = threadIdx.y;
    const int l = l0 + ty, s = s0 + tx;

    bool val = false;
    if (l < TT && s < TT) {
        size_t idx = ((size_t)n * TT + l) * TT + s;
        if      (kind == 0) val = ((const uint8_t*)m)[idx] != 0;
        else if (kind == 1) val = ((const int*)m)[idx] != 0;
        else if (kind == 2) val = ((const float*)m)[idx] != 0.0f;
        else                val = ((const unsigned short*)m)[idx] != 0;
    }

    unsigned w0 = __ballot_sync(0xFFFFFFFFu, val);
    if (tx == 0 && l < TT)
        g_mb0[((size_t)n * MW + blockIdx.x) * TT + l] = w0;

    tile[ty][tx] = val ? 1 : 0;
    __syncthreads();

    bool valT = tile[tx][ty] != 0;
    unsigned w1 = __ballot_sync(0xFFFFFFFFu, valT);
    if (tx == 0 && (s0 + ty) < TT)
        g_mb1[((size_t)n * MW + blockIdx.y) * TT + s0 + ty] = w1;
}

// ============================================================================
// 1) Projection: p = x @ W_proj + b_proj -> per-head q/v layout,
//    TF32-PRE-ROUNDED on store (flash consumes raw bit patterns).
//    128x64 block tile, 8x4 per thread.  grid (8, 47, 2) block 256.
// ============================================================================
__global__ void proj_kernel(const float* __restrict__ x0,
                            const float* __restrict__ x1,
                            const float* __restrict__ W,
                            const float* __restrict__ bias)
{
    const float* x  = blockIdx.z ? x1 : x0;
    float*       qh = blockIdx.z ? g_q1 : g_q0;
    float*       vh = blockIdx.z ? g_v1 : g_v0;

    __shared__ float As[16][132];   // [k][row], pad for bank spread
    __shared__ float Bs[16][64];

    const int tid = threadIdx.x;
    const int tx = tid & 15, ty = tid >> 4;
    const int bm = blockIdx.y * 128, bn = blockIdx.x * 64;

    const int arow = tid >> 1, akc = (tid & 1) * 8;   // 2 float4 per thread
    const int brow = tid >> 4, bnc = (tid & 15) * 4;

    float2 c2[8][2];
    #pragma unroll
    for (int i = 0; i < 8; ++i) { c2[i][0] = make_float2(0.f,0.f); c2[i][1] = make_float2(0.f,0.f); }

    for (int kt = 0; kt < CC; kt += 16) {
        int gr = bm + arow;
        float4 a0 = make_float4(0.f,0.f,0.f,0.f), a1 = a0;
        if (gr < MROW) {
            a0 = *(const float4*)(x + (size_t)gr * CC + kt + akc);
            a1 = *(const float4*)(x + (size_t)gr * CC + kt + akc + 4);
        }
        As[akc + 0][arow] = a0.x; As[akc + 1][arow] = a0.y;
        As[akc + 2][arow] = a0.z; As[akc + 3][arow] = a0.w;
        As[akc + 4][arow] = a1.x; As[akc + 5][arow] = a1.y;
        As[akc + 6][arow] = a1.z; As[akc + 7][arow] = a1.w;
        *(float4*)&Bs[brow][bnc] =
            *(const float4*)(W + (size_t)(kt + brow) * (2 * HH) + bn + bnc);
        __syncthreads();
        #pragma unroll
        for (int k = 0; k < 16; ++k) {
            float4 av0 = *(float4*)&As[k][ty * 8];
            float4 av1 = *(float4*)&As[k][ty * 8 + 4];
            float4 bv  = *(float4*)&Bs[k][tx * 4];
            float2 b01 = make_float2(bv.x, bv.y), b23 = make_float2(bv.z, bv.w);
            float a[8] = { av0.x, av0.y, av0.z, av0.w, av1.x, av1.y, av1.z, av1.w };
            #pragma unroll
            for (int i = 0; i < 8; ++i) {
                float2 aa = make_float2(a[i], a[i]);
                c2[i][0] = ffma2(aa, b01, c2[i][0]);
                c2[i][1] = ffma2(aa, b23, c2[i][1]);
            }
        }
        __syncthreads();
    }

    #pragma unroll
    for (int i = 0; i < 8; ++i) {
        int gr = bm + ty * 8 + i;
        if (gr >= MROW) continue;
        int n = gr / TT, t = gr % TT;
        float cv[4] = { c2[i][0].x, c2[i][0].y, c2[i][1].x, c2[i][1].y };
        #pragma unroll
        for (int j = 0; j < 4; ++j) {
            int gc = bn + tx * 4 + j;
            float v = tf32f(cv[j] + bias[gc]);   // pre-round for flash mma
            int cc = gc & 255;
            int f = cc >> 5, d = cc & 31;
            float* dst = (gc < HH) ? qh : vh;
            dst[((size_t)(n * FCH + f) * TT + t) * DD + d] = v;
        }
    }
}

// ============================================================================
// 2) Flash attention on tensor cores. K/V arrive TF32-PRE-ROUNDED from proj:
//    no conversion work in the loop, ONE sync per tile.
//    QK: 1-term.  PV: 1-term.  No-max softmax.
//    Block = 4 warps; 16 q-rows/warp (BR=64), BC=64 per tile, 47 tiles.
//    grid (47, 16, 2) block 128.
// ============================================================================
__global__ void __launch_bounds__(128)
flashmma_kernel()
{
    const int dir  = blockIdx.z;
    const float*    Q  = dir ? g_q1 : g_q0;
    const float*    Kg = dir ? g_q0 : g_q1;
    const float*    Vg = dir ? g_v0 : g_v1;
    const unsigned* Mb = dir ? g_mb1 : g_mb0;
    float*          O  = dir ? g_m1 : g_m0;

    const int head = blockIdx.y;          // 0..15
    const int n    = head >> 3;
    const int tid  = threadIdx.x;
    const int wid  = tid >> 5;
    const int lane = tid & 31;
    const int g    = lane >> 2;           // groupID (row within 8)
    const int tg   = lane & 3;            // thread-in-group

    const int r0 = blockIdx.x * 64 + wid * 16 + g;   // always < 3000
    const int r1 = r0 + 8;                           // may be >= 3000 in last block
    const int rB = (r1 < TT) ? r1 : (TT - 1);

    // K stride 36, V stride 40, mini-P stride 12: conflict-free patterns
    __shared__ __align__(16) float Ks[2][64 * 36];
    __shared__ __align__(16) float Vs[2][64 * 40];
    __shared__ __align__(16) float Ps[4][16 * 12];

    const float* Qh = Q  + (size_t)head * TT * DD;
    const float* Kh = Kg + (size_t)head * TT * DD;
    const float* Vh = Vg + (size_t)head * TT * DD;

    // ---- Q fragments: scale pre-rounded q by QSCALE, round to tf32 ----
    uint32_t qhf[4][4];
    #pragma unroll
    for (int c = 0; c < 4; ++c) {
        int col = c * 8 + tg;
        qhf[c][0] = tf32r(Qh[(size_t)r0 * DD + col]     * QSCALE);
        qhf[c][1] = tf32r(Qh[(size_t)rB * DD + col]     * QSCALE);
        qhf[c][2] = tf32r(Qh[(size_t)r0 * DD + col + 4] * QSCALE);
        qhf[c][3] = tf32r(Qh[(size_t)rB * DD + col + 4] * QSCALE);
    }

    auto load_tile = [&](int tile, int buf) {
        int s0 = tile * 64;
        #pragma unroll
        for (int k = 0; k < 4; ++k) {
            int idx = tid + k * 128;             // 512 chunks: 64 rows x 8
            int s = idx >> 3, dc = (idx & 7) * 4;
            int sg = s0 + s;
            if (sg < TT) {
                cp16(&Ks[buf][s * 36 + dc], Kh + (size_t)sg * DD + dc);
                cp16(&Vs[buf][s * 40 + dc], Vh + (size_t)sg * DD + dc);
            } else {
                float4 z = make_float4(0.f, 0.f, 0.f, 0.f);
                *(float4*)&Ks[buf][s * 36 + dc] = z;
                *(float4*)&Vs[buf][s * 40 + dc] = z;
            }
        }
        asm volatile("cp.async.commit_group;" ::: "memory");
    };

    load_tile(0, 0);

    float o[4][4];
    #pragma unroll
    for (int i = 0; i < 4; ++i)
        #pragma unroll
        for (int j = 0; j < 4; ++j) o[i][j] = 0.f;
    float lr0 = 0.f, lr1 = 0.f;

    const unsigned* mbase = Mb + (size_t)n * MW * TT;
    float* Pw = &Ps[wid][0];

    for (int tile = 0; tile < 47; ++tile) {
        const int buf = tile & 1;
        if (tile + 1 < 47) {
            load_tile(tile + 1, buf ^ 1);
            asm volatile("cp.async.wait_group 1;" ::: "memory");
        } else {
            asm volatile("cp.async.wait_group 0;" ::: "memory");
        }
        __syncthreads();

        // mask words for this tile (BC=64 = exactly 2 words, tile-aligned)
        unsigned mw00 = mbase[(size_t)(2 * tile)     * TT + r0];
        unsigned mw01 = mbase[(size_t)(2 * tile + 1) * TT + r0];
        unsigned mw10 = mbase[(size_t)(2 * tile)     * TT + rB];
        unsigned mw11 = mbase[(size_t)(2 * tile + 1) * TT + rB];

        const float* Kb = &Ks[buf][0];
        const float* Vb = &Vs[buf][0];

        #pragma unroll 2
        for (int j = 0; j < 8; ++j) {
            // ---- QK^T: 1-term (operands pre-rounded in gmem/smem) ----
            float c0 = 0.f, c1 = 0.f, c2 = 0.f, c3 = 0.f;
            #pragma unroll
            for (int cc = 0; cc < 4; ++cc) {
                uint32_t bh0 = fui(Kb[(j * 8 + g) * 36 + cc * 8 + tg]);
                uint32_t bh1 = fui(Kb[(j * 8 + g) * 36 + cc * 8 + tg + 4]);
                mma_tf32(c0, c1, c2, c3, qhf[cc][0], qhf[cc][1], qhf[cc][2], qhf[cc][3], bh0, bh1);
            }

            // ---- masked exp (no-max: scores bounded) ----
            unsigned m0 = (j & 4) ? mw01 : mw00;
            unsigned m1 = (j & 4) ? mw11 : mw10;
            int sh = (j * 8 + 2 * tg) & 31;
            float p0 = ((m0 >> sh)       & 1u) ? ex2f(c0) : 0.f;
            float p1 = ((m0 >> (sh + 1)) & 1u) ? ex2f(c1) : 0.f;
            float p2 = ((m1 >> sh)       & 1u) ? ex2f(c2) : 0.f;
            float p3 = ((m1 >> (sh + 1)) & 1u) ? ex2f(c3) : 0.f;
            lr0 += p0 + p1;
            lr1 += p2 + p3;

            // ---- redistribute P (C-layout -> A-layout), tf32-rounded ----
            *(float2*)&Pw[g * 12 + 2 * tg]       = make_float2(p0, p1);
            *(float2*)&Pw[(g + 8) * 12 + 2 * tg] = make_float2(p2, p3);
            __syncwarp();
            uint32_t ah0 = tf32r(Pw[g * 12 + tg]);
            uint32_t ah1 = tf32r(Pw[(g + 8) * 12 + tg]);
            uint32_t ah2 = tf32r(Pw[g * 12 + tg + 4]);
            uint32_t ah3 = tf32r(Pw[(g + 8) * 12 + tg + 4]);

            // ---- PV: O[16x32] += P * V (V pre-rounded) ----
            #pragma unroll
            for (int nt = 0; nt < 4; ++nt) {
                uint32_t vh0 = fui(Vb[(j * 8 + tg) * 40 + nt * 8 + g]);
                uint32_t vh1 = fui(Vb[(j * 8 + tg + 4) * 40 + nt * 8 + g]);
                mma_tf32(o[nt][0], o[nt][1], o[nt][2], o[nt][3], ah0, ah1, ah2, ah3, vh0, vh1);
            }
            __syncwarp();
        }
        __syncthreads();   // all warps done with buf before it is overwritten
    }

    // ---- row sums: reduce over the 4 threads sharing each row ----
    lr0 += __shfl_xor_sync(0xFFFFFFFFu, lr0, 1);
    lr0 += __shfl_xor_sync(0xFFFFFFFFu, lr0, 2);
    lr1 += __shfl_xor_sync(0xFFFFFFFFu, lr1, 1);
    lr1 += __shfl_xor_sync(0xFFFFFFFFu, lr1, 2);
    float inv0 = (lr0 > 0.f) ? 1.f / lr0 : 0.f;   // all-masked row -> 0
    float inv1 = (lr1 > 0.f) ? 1.f / lr1 : 0.f;

    float* Oh = O + (size_t)head * TT * DD;
    #pragma unroll
    for (int nt = 0; nt < 4; ++nt) {
        int d0 = nt * 8 + 2 * tg;
        *(float2*)&Oh[(size_t)r0 * DD + d0] =
            make_float2(o[nt][0] * inv0, o[nt][1] * inv0);
        if (r1 < TT)
            *(float2*)&Oh[(size_t)r1 * DD + d0] =
                make_float2(o[nt][2] * inv1, o[nt][3] * inv1);
    }
}

// ============================================================================
// 3) Merge: out = concat_heads(m) @ W_merge + b_merge
//    128x64 block tile, 8x4 per thread.  grid (4, 47, 2) block 256.
// ============================================================================
__global__ void merge_kernel(const float* __restrict__ W,
                             const float* __restrict__ bias,
                             float* __restrict__ out)
{
    const float* A = blockIdx.z ? g_m1 : g_m0;
    float* o = out + (size_t)blockIdx.z * MROW * CC;

    __shared__ float As[16][132];
    __shared__ float Bs[16][64];

    const int tid = threadIdx.x;
    const int tx = tid & 15, ty = tid >> 4;
    const int bm = blockIdx.y * 128, bn = blockIdx.x * 64;

    const int arow = tid >> 1, akc = (tid & 1) * 8;
    const int brow = tid >> 4, bnc = (tid & 15) * 4;

    float2 c2[8][2];
    #pragma unroll
    for (int i = 0; i < 8; ++i) { c2[i][0] = make_float2(0.f,0.f); c2[i][1] = make_float2(0.f,0.f); }

    for (int kt = 0; kt < HH; kt += 16) {
        int gr = bm + arow;
        int gk = kt + akc;                    // hidden index = f*32 + d (8-aligned)
        float4 a0 = make_float4(0.f,0.f,0.f,0.f), a1 = a0;
        if (gr < MROW) {
            int n = gr / TT, t = gr % TT;
            int f = gk >> 5, d = gk & 31;
            const float* src = A + ((size_t)(n * FCH + f) * TT + t) * DD + d;
            a0 = *(const float4*)(src);
            a1 = *(const float4*)(src + 4);
        }
        As[akc + 0][arow] = a0.x; As[akc + 1][arow] = a0.y;
        As[akc + 2][arow] = a0.z; As[akc + 3][arow] = a0.w;
        As[akc + 4][arow] = a1.x; As[akc + 5][arow] = a1.y;
        As[akc + 6][arow] = a1.z; As[akc + 7][arow] = a1.w;
        *(float4*)&Bs[brow][bnc] =
            *(const float4*)(W + (size_t)(kt + brow) * CC + bn + bnc);
        __syncthreads();
        #pragma unroll
        for (int k = 0; k < 16; ++k) {
            float4 av0 = *(float4*)&As[k][ty * 8];
            float4 av1 = *(float4*)&As[k][ty * 8 + 4];
            float4 bv  = *(float4*)&Bs[k][tx * 4];
            float2 b01 = make_float2(bv.x, bv.y), b23 = make_float2(bv.z, bv.w);
            float a[8] = { av0.x, av0.y, av0.z, av0.w, av1.x, av1.y, av1.z, av1.w };
            #pragma unroll
            for (int i = 0; i < 8; ++i) {
                float2 aa = make_float2(a[i], a[i]);
                c2[i][0] = ffma2(aa, b01, c2[i][0]);
                c2[i][1] = ffma2(aa, b23, c2[i][1]);
            }
        }
        __syncthreads();
    }

    #pragma unroll
    for (int i = 0; i < 8; ++i) {
        int gr = bm + ty * 8 + i;
        if (gr >= MROW) continue;
        float cv[4] = { c2[i][0].x, c2[i][0].y, c2[i][1].x, c2[i][1].y };
        #pragma unroll
        for (int j = 0; j < 4; ++j) {
            int gc = bn + tx * 4 + j;
            o[(size_t)gr * CC + gc] = cv[j] + bias[gc];
        }
    }
}

// ============================================================================
// launch
// ============================================================================
extern "C" void kernel_launch(void* const* d_in, const int* in_sizes, int n_in,
                              void* d_out, int out_size)
{
    const float* x0   = (const float*)d_in[0];
    const float* x1   = (const float*)d_in[1];
    const void*  mask = (const void*)d_in[2];
    const float* Wp   = (const float*)d_in[3];
    const float* bp   = (const float*)d_in[4];
    const float* Wm   = (const float*)d_in[5];
    const float* bmg  = (const float*)d_in[6];
    float* out = (float*)d_out;

    // 0) mask dtype detect (parallel) + bit-pack both orientations
    mzero_kernel<<<1, 1>>>();
    detect_kernel<<<64, 256>>>((const unsigned*)mask);
    pack_kernel<<<dim3(94, 94, 2), dim3(32, 32)>>>(mask);

    // 1) projection + head split, tf32-pre-rounded outputs
    proj_kernel<<<dim3(8, 47, 2), 256>>>(x0, x1, Wp, bp);

    // 2) bidirectional flash attention on tensor cores
    flashmma_kernel<<<dim3(47, NF, 2), 128>>>();

    // 3) merge heads + output projection (m0 -> first half, m1 -> second)
    merge_kernel<<<dim3(4, 47, 2), 256>>>(Wm, bmg, out);
}